// round 1
// baseline (speedup 1.0000x reference)
#include <cuda_runtime.h>
#include <math.h>

#define B_SZ 2
#define NSEQ 2048
#define DMODEL 1024
#define NH 16
#define HD 64
#define MROWS (B_SZ * NSEQ)   // 4096

// ---------------- scratch (static device globals; no allocation) ----------------
__device__ float g_qkv[(size_t)MROWS * 3 * DMODEL];           // 50.3 MB
__device__ float g_q[(size_t)B_SZ * NH * NSEQ * HD];          // 16.8 MB  [B,H,N,d]
__device__ float g_k[(size_t)B_SZ * NH * NSEQ * HD];
__device__ float g_v[(size_t)B_SZ * NH * NSEQ * HD];
__device__ float g_o[(size_t)MROWS * DMODEL];                 // [B,N,D]

// ---------------- generic tiled SGEMM + bias:  C = A @ B + bias ----------------
// A[M,K], B[K,N], bias[N], C[M,N].  All dims divisible by tiles.
__global__ __launch_bounds__(256) void sgemm_bias(
    const float* __restrict__ A, const float* __restrict__ Bm,
    const float* __restrict__ bias, float* __restrict__ C,
    int M, int N, int K)
{
    constexpr int BM = 128, BN = 128, BK = 16, TM = 8, TN = 8;
    __shared__ float As[BK][BM];   // A transposed: As[k][m]
    __shared__ float Bs[BK][BN];
    const int tid  = threadIdx.x;
    const int tcol = tid & 15;     // 0..15
    const int trow = tid >> 4;     // 0..15
    const int rowBase = blockIdx.y * BM;
    const int colBase = blockIdx.x * BN;

    float acc[TM][TN];
#pragma unroll
    for (int i = 0; i < TM; i++)
#pragma unroll
        for (int j = 0; j < TN; j++) acc[i][j] = 0.0f;

    for (int k0 = 0; k0 < K; k0 += BK) {
        // Load A tile (BM x BK) transposed into As
#pragma unroll
        for (int it = 0; it < 2; it++) {
            int idx = it * 256 + tid;
            int r = idx >> 2;            // 0..127
            int c = (idx & 3) << 2;      // 0,4,8,12
            float4 v = *reinterpret_cast<const float4*>(
                &A[(size_t)(rowBase + r) * K + k0 + c]);
            As[c + 0][r] = v.x;
            As[c + 1][r] = v.y;
            As[c + 2][r] = v.z;
            As[c + 3][r] = v.w;
        }
        // Load B tile (BK x BN)
#pragma unroll
        for (int it = 0; it < 2; it++) {
            int idx = it * 256 + tid;
            int r = idx >> 5;            // 0..15
            int c = (idx & 31) << 2;     // 0..124
            *reinterpret_cast<float4*>(&Bs[r][c]) =
                *reinterpret_cast<const float4*>(
                    &Bm[(size_t)(k0 + r) * N + colBase + c]);
        }
        __syncthreads();

#pragma unroll
        for (int kk = 0; kk < BK; kk++) {
            float a[TM], b[TN];
            *reinterpret_cast<float4*>(&a[0]) = *reinterpret_cast<float4*>(&As[kk][trow * TM]);
            *reinterpret_cast<float4*>(&a[4]) = *reinterpret_cast<float4*>(&As[kk][trow * TM + 4]);
            *reinterpret_cast<float4*>(&b[0]) = *reinterpret_cast<float4*>(&Bs[kk][tcol * TN]);
            *reinterpret_cast<float4*>(&b[4]) = *reinterpret_cast<float4*>(&Bs[kk][tcol * TN + 4]);
#pragma unroll
            for (int i = 0; i < TM; i++)
#pragma unroll
                for (int j = 0; j < TN; j++)
                    acc[i][j] += a[i] * b[j];
        }
        __syncthreads();
    }

    // Epilogue: + bias, store
#pragma unroll
    for (int i = 0; i < TM; i++) {
        int row = rowBase + trow * TM + i;
#pragma unroll
        for (int j = 0; j < TN; j += 4) {
            int col = colBase + tcol * TN + j;
            float4 bv = *reinterpret_cast<const float4*>(&bias[col]);
            float4 r;
            r.x = acc[i][j + 0] + bv.x;
            r.y = acc[i][j + 1] + bv.y;
            r.z = acc[i][j + 2] + bv.z;
            r.w = acc[i][j + 3] + bv.w;
            *reinterpret_cast<float4*>(&C[(size_t)row * N + col]) = r;
        }
    }
}

// ------------- fused RMSNorm(q,k over D) + RoPE + head-layout scatter -------------
// One block per (b,n) row. Writes g_q/g_k/g_v in [B,H,N,d] layout.
__global__ __launch_bounds__(256) void rms_rope_kernel(
    const float* __restrict__ cosT, const float* __restrict__ sinT,
    const float* __restrict__ q_scale, const float* __restrict__ k_scale)
{
    const int row = blockIdx.x;            // b*NSEQ + n
    const int b = row / NSEQ;
    const int n = row % NSEQ;
    const float* qr = g_qkv + (size_t)row * 3 * DMODEL;
    const float* kr = qr + DMODEL;
    const float* vr = qr + 2 * DMODEL;

    // sum of squares for q and k rows (DMODEL = 1024, 256 threads * float4)
    float sq = 0.0f, sk = 0.0f;
    for (int i = threadIdx.x * 4; i < DMODEL; i += 256 * 4) {
        float4 q4 = *reinterpret_cast<const float4*>(&qr[i]);
        float4 k4 = *reinterpret_cast<const float4*>(&kr[i]);
        sq += q4.x * q4.x + q4.y * q4.y + q4.z * q4.z + q4.w * q4.w;
        sk += k4.x * k4.x + k4.y * k4.y + k4.z * k4.z + k4.w * k4.w;
    }
#pragma unroll
    for (int off = 16; off >= 1; off >>= 1) {
        sq += __shfl_xor_sync(0xffffffffu, sq, off);
        sk += __shfl_xor_sync(0xffffffffu, sk, off);
    }
    __shared__ float wq[8], wk[8];
    __shared__ float s_iq, s_ik;
    int wid = threadIdx.x >> 5, lid = threadIdx.x & 31;
    if (lid == 0) { wq[wid] = sq; wk[wid] = sk; }
    __syncthreads();
    if (threadIdx.x == 0) {
        float a = 0.0f, c = 0.0f;
#pragma unroll
        for (int w = 0; w < 8; w++) { a += wq[w]; c += wk[w]; }
        s_iq = rsqrtf(a / (float)DMODEL + 1e-6f);
        s_ik = rsqrtf(c / (float)DMODEL + 1e-6f);
    }
    __syncthreads();
    const float iq = s_iq, ik = s_ik;

    // RoPE over interleaved pairs; scatter into [B,H,N,d]
    for (int p = threadIdx.x; p < DMODEL / 2; p += 256) {
        int h = p >> 5;                    // head (32 pairs per head)
        int j = p & 31;                    // pair index within head
        int i0 = h * HD + 2 * j;
        float c = cosT[n * 32 + j];
        float s = sinT[n * 32 + j];
        float q0 = qr[i0]     * iq * q_scale[i0];
        float q1 = qr[i0 + 1] * iq * q_scale[i0 + 1];
        float k0 = kr[i0]     * ik * k_scale[i0];
        float k1 = kr[i0 + 1] * ik * k_scale[i0 + 1];
        size_t base = (((size_t)b * NH + h) * NSEQ + n) * HD + 2 * j;
        g_q[base]     = q0 * c - q1 * s;
        g_q[base + 1] = q0 * s + q1 * c;
        g_k[base]     = k0 * c - k1 * s;
        g_k[base + 1] = k0 * s + k1 * c;
    }
    // v: pure layout scatter
    for (int i = threadIdx.x * 4; i < DMODEL; i += 1024) {
        float4 v4 = *reinterpret_cast<const float4*>(&vr[i]);
        int h = i >> 6;
        int c = i & 63;
        *reinterpret_cast<float4*>(
            &g_v[(((size_t)b * NH + h) * NSEQ + n) * HD + c]) = v4;
    }
}

// ---------------- FlashAttention-2 style fp32 attention ----------------
// grid: (N/128, NH, B). 256 threads as 16x16. BQ=BK=128, d=64.
__global__ __launch_bounds__(256) void attn_kernel()
{
    extern __shared__ float sm[];
    float* Qt = sm;                    // [64][128]  transposed, pre-scaled
    float* Kt = Qt + 64 * 128;         // [64][128]  transposed
    float* Vs = Kt + 64 * 128;         // [128][64]
    float* Ss = Vs + 128 * 64;         // [128][128] P matrix

    const int tid = threadIdx.x;
    const int tx = tid & 15;           // k-direction / d-direction
    const int ty = tid >> 4;           // q-direction
    const int h = blockIdx.y, b = blockIdx.z;
    const size_t bhBase = ((size_t)b * NH + h) * (size_t)NSEQ * HD;
    const float* Qg = g_q + bhBase + (size_t)blockIdx.x * 128 * HD;
    const float* Kg = g_k + bhBase;
    const float* Vg = g_v + bhBase;
    const float scale = 0.125f;        // 1/sqrt(64)

    // Load Q tile transposed + scaled
#pragma unroll
    for (int it = 0; it < 8; it++) {
        int idx = it * 256 + tid;
        int r = idx >> 4;              // 0..127
        int c = (idx & 15) << 2;       // 0..60
        float4 v = *reinterpret_cast<const float4*>(&Qg[r * HD + c]);
        Qt[(c + 0) * 128 + r] = v.x * scale;
        Qt[(c + 1) * 128 + r] = v.y * scale;
        Qt[(c + 2) * 128 + r] = v.z * scale;
        Qt[(c + 3) * 128 + r] = v.w * scale;
    }

    float m[8], l[8], o[8][4];
#pragma unroll
    for (int i = 0; i < 8; i++) {
        m[i] = -3.402823466e38f;
        l[i] = 0.0f;
#pragma unroll
        for (int c = 0; c < 4; c++) o[i][c] = 0.0f;
    }

    for (int kt = 0; kt < NSEQ / 128; kt++) {
        __syncthreads();   // prev PV done (and Qt visible on first iter)
        const float* Kgt = Kg + (size_t)kt * 128 * HD;
        const float* Vgt = Vg + (size_t)kt * 128 * HD;
#pragma unroll
        for (int it = 0; it < 8; it++) {
            int idx = it * 256 + tid;
            int r = idx >> 4;
            int c = (idx & 15) << 2;
            float4 kv = *reinterpret_cast<const float4*>(&Kgt[r * HD + c]);
            Kt[(c + 0) * 128 + r] = kv.x;
            Kt[(c + 1) * 128 + r] = kv.y;
            Kt[(c + 2) * 128 + r] = kv.z;
            Kt[(c + 3) * 128 + r] = kv.w;
            float4 vv = *reinterpret_cast<const float4*>(&Vgt[r * HD + c]);
            *reinterpret_cast<float4*>(&Vs[r * HD + c]) = vv;
        }
        __syncthreads();

        // S = (Q*scale) @ K^T   (128x128, 8x8 per thread)
        float s[8][8];
#pragma unroll
        for (int i = 0; i < 8; i++)
#pragma unroll
            for (int j = 0; j < 8; j++) s[i][j] = 0.0f;

#pragma unroll 4
        for (int c = 0; c < HD; c++) {
            float a[8], bb[8];
            *reinterpret_cast<float4*>(&a[0])  = *reinterpret_cast<float4*>(&Qt[c * 128 + ty * 8]);
            *reinterpret_cast<float4*>(&a[4])  = *reinterpret_cast<float4*>(&Qt[c * 128 + ty * 8 + 4]);
            *reinterpret_cast<float4*>(&bb[0]) = *reinterpret_cast<float4*>(&Kt[c * 128 + tx * 8]);
            *reinterpret_cast<float4*>(&bb[4]) = *reinterpret_cast<float4*>(&Kt[c * 128 + tx * 8 + 4]);
#pragma unroll
            for (int i = 0; i < 8; i++)
#pragma unroll
                for (int j = 0; j < 8; j++)
                    s[i][j] += a[i] * bb[j];
        }

        // Online softmax. Row reduction across the 16 tx lanes (same warp half).
#pragma unroll
        for (int i = 0; i < 8; i++) {
            float mt = s[i][0];
#pragma unroll
            for (int j = 1; j < 8; j++) mt = fmaxf(mt, s[i][j]);
#pragma unroll
            for (int off = 8; off >= 1; off >>= 1)
                mt = fmaxf(mt, __shfl_xor_sync(0xffffffffu, mt, off));
            float mn = fmaxf(m[i], mt);
            float alpha = __expf(m[i] - mn);
            m[i] = mn;
            float ls = 0.0f;
#pragma unroll
            for (int j = 0; j < 8; j++) {
                float p = __expf(s[i][j] - mn);
                s[i][j] = p;
                ls += p;
            }
#pragma unroll
            for (int off = 8; off >= 1; off >>= 1)
                ls += __shfl_xor_sync(0xffffffffu, ls, off);
            l[i] = l[i] * alpha + ls;
#pragma unroll
            for (int c = 0; c < 4; c++) o[i][c] *= alpha;
            *reinterpret_cast<float4*>(&Ss[(ty * 8 + i) * 128 + tx * 8]) =
                make_float4(s[i][0], s[i][1], s[i][2], s[i][3]);
            *reinterpret_cast<float4*>(&Ss[(ty * 8 + i) * 128 + tx * 8 + 4]) =
                make_float4(s[i][4], s[i][5], s[i][6], s[i][7]);
        }
        __syncthreads();

        // O += P @ V   (each thread: 8 q rows x 4 d cols)
#pragma unroll 2
        for (int j = 0; j < 128; j += 4) {
            float4 v0 = *reinterpret_cast<float4*>(&Vs[(j + 0) * HD + tx * 4]);
            float4 v1 = *reinterpret_cast<float4*>(&Vs[(j + 1) * HD + tx * 4]);
            float4 v2 = *reinterpret_cast<float4*>(&Vs[(j + 2) * HD + tx * 4]);
            float4 v3 = *reinterpret_cast<float4*>(&Vs[(j + 3) * HD + tx * 4]);
#pragma unroll
            for (int i = 0; i < 8; i++) {
                float4 p = *reinterpret_cast<float4*>(&Ss[(ty * 8 + i) * 128 + j]);
                o[i][0] += p.x * v0.x + p.y * v1.x + p.z * v2.x + p.w * v3.x;
                o[i][1] += p.x * v0.y + p.y * v1.y + p.z * v2.y + p.w * v3.y;
                o[i][2] += p.x * v0.z + p.y * v1.z + p.z * v2.z + p.w * v3.z;
                o[i][3] += p.x * v0.w + p.y * v1.w + p.z * v2.w + p.w * v3.w;
            }
        }
    }

    // Epilogue: normalize and scatter to [B,N,D]
#pragma unroll
    for (int i = 0; i < 8; i++) {
        float inv = 1.0f / l[i];
        int q = blockIdx.x * 128 + ty * 8 + i;
        size_t row = (size_t)b * NSEQ + q;
        float4 r = make_float4(o[i][0] * inv, o[i][1] * inv, o[i][2] * inv, o[i][3] * inv);
        *reinterpret_cast<float4*>(&g_o[row * DMODEL + h * HD + tx * 4]) = r;
    }
}

// ---------------- launch ----------------
extern "C" void kernel_launch(void* const* d_in, const int* in_sizes, int n_in,
                              void* d_out, int out_size)
{
    const float* x       = (const float*)d_in[0];
    const float* cosT    = (const float*)d_in[1];
    const float* sinT    = (const float*)d_in[2];
    const float* Wqkv    = (const float*)d_in[3];
    const float* bqkv    = (const float*)d_in[4];
    const float* q_scale = (const float*)d_in[5];
    const float* k_scale = (const float*)d_in[6];
    const float* Wout    = (const float*)d_in[7];
    const float* bout    = (const float*)d_in[8];
    float* out = (float*)d_out;

    float *qkv_p, *o_p;
    cudaGetSymbolAddress((void**)&qkv_p, g_qkv);
    cudaGetSymbolAddress((void**)&o_p, g_o);

    const int attn_smem = (64 * 128 + 64 * 128 + 128 * 64 + 128 * 128) * 4; // 163840
    cudaFuncSetAttribute(attn_kernel,
                         cudaFuncAttributeMaxDynamicSharedMemorySize, attn_smem);

    // 1) QKV GEMM: [4096,1024] @ [1024,3072] + bqkv
    sgemm_bias<<<dim3(3 * DMODEL / 128, MROWS / 128), 256>>>(
        x, Wqkv, bqkv, qkv_p, MROWS, 3 * DMODEL, DMODEL);

    // 2) RMSNorm + RoPE + layout
    rms_rope_kernel<<<MROWS, 256>>>(cosT, sinT, q_scale, k_scale);

    // 3) Attention
    attn_kernel<<<dim3(NSEQ / 128, NH, B_SZ), 256, attn_smem>>>();

    // 4) Output GEMM: [4096,1024] @ [1024,1024] + bout
    sgemm_bias<<<dim3(DMODEL / 128, MROWS / 128), 256>>>(
        o_p, Wout, bout, out, MROWS, DMODEL, DMODEL);
}

// round 4
// speedup vs baseline: 1.3626x; 1.3626x over previous
#include <cuda_runtime.h>
#include <cuda_bf16.h>
#include <cstdint>
#include <math.h>

#define B_SZ 2
#define NSEQ 2048
#define DMODEL 1024
#define NH 16
#define HD 64
#define MROWS (B_SZ * NSEQ)   // 4096

// ---------------- scratch (static device globals; no allocation) ----------------
__device__ float g_qkv[(size_t)MROWS * 3 * DMODEL];
__device__ float g_q[(size_t)B_SZ * NH * NSEQ * HD];          // [B,H,N,d]
__device__ float g_k[(size_t)B_SZ * NH * NSEQ * HD];
__device__ float g_v[(size_t)B_SZ * NH * NSEQ * HD];
__device__ float g_o[(size_t)MROWS * DMODEL];                 // [B,N,D]

// bf16 split operands
__device__ __nv_bfloat16 g_xh[(size_t)MROWS * DMODEL];
__device__ __nv_bfloat16 g_xl[(size_t)MROWS * DMODEL];
__device__ __nv_bfloat16 g_oh[(size_t)MROWS * DMODEL];
__device__ __nv_bfloat16 g_ol[(size_t)MROWS * DMODEL];
__device__ __nv_bfloat16 g_wqh[(size_t)3 * DMODEL * DMODEL];  // Wqkv^T  [3072][1024]
__device__ __nv_bfloat16 g_wql[(size_t)3 * DMODEL * DMODEL];
__device__ __nv_bfloat16 g_woh[(size_t)DMODEL * DMODEL];      // Wout^T  [1024][1024]
__device__ __nv_bfloat16 g_wol[(size_t)DMODEL * DMODEL];

// ---------------- helpers (base sm_100-safe: mma.sync / ldmatrix / cp.async) ----------------
__device__ __forceinline__ uint32_t smem_u32(const void* p) {
    uint32_t a;
    asm("{ .reg .u64 t; cvta.to.shared.u64 t, %1; cvt.u32.u64 %0, t; }"
        : "=r"(a) : "l"(p));
    return a;
}
__device__ __forceinline__ void cpa16(uint32_t s, const void* g) {
    asm volatile("cp.async.cg.shared.global [%0], [%1], 16;" :: "r"(s), "l"(g));
}
#define CP_COMMIT() asm volatile("cp.async.commit_group;" ::: "memory")
#define CP_WAIT(n)  asm volatile("cp.async.wait_group %0;" :: "n"(n) : "memory")

__device__ __forceinline__ void ldm_x4(uint32_t* r, uint32_t addr) {
    asm volatile("ldmatrix.sync.aligned.m8n8.x4.shared.b16 {%0,%1,%2,%3}, [%4];"
        : "=r"(r[0]), "=r"(r[1]), "=r"(r[2]), "=r"(r[3]) : "r"(addr));
}
__device__ __forceinline__ void ldm_x2(uint32_t& r0, uint32_t& r1, uint32_t addr) {
    asm volatile("ldmatrix.sync.aligned.m8n8.x2.shared.b16 {%0,%1}, [%2];"
        : "=r"(r0), "=r"(r1) : "r"(addr));
}
__device__ __forceinline__ void mma16816(float* d, const uint32_t* a,
                                         uint32_t b0, uint32_t b1) {
    asm volatile(
        "mma.sync.aligned.m16n8k16.row.col.f32.bf16.bf16.f32 "
        "{%0,%1,%2,%3}, {%4,%5,%6,%7}, {%8,%9}, {%0,%1,%2,%3};"
        : "+f"(d[0]), "+f"(d[1]), "+f"(d[2]), "+f"(d[3])
        : "r"(a[0]), "r"(a[1]), "r"(a[2]), "r"(a[3]), "r"(b0), "r"(b1));
}

// ---------------- split kernels ----------------
__global__ __launch_bounds__(256) void split_kernel(
    const float* __restrict__ s, __nv_bfloat16* __restrict__ h,
    __nv_bfloat16* __restrict__ l, int n)
{
    int i = (blockIdx.x * 256 + threadIdx.x) * 4;
    if (i >= n) return;
    float4 v = *reinterpret_cast<const float4*>(s + i);
    __nv_bfloat16 h0 = __float2bfloat16(v.x), h1 = __float2bfloat16(v.y);
    __nv_bfloat16 h2 = __float2bfloat16(v.z), h3 = __float2bfloat16(v.w);
    __nv_bfloat16 l0 = __float2bfloat16(v.x - __bfloat162float(h0));
    __nv_bfloat16 l1 = __float2bfloat16(v.y - __bfloat162float(h1));
    __nv_bfloat16 l2 = __float2bfloat16(v.z - __bfloat162float(h2));
    __nv_bfloat16 l3 = __float2bfloat16(v.w - __bfloat162float(h3));
    __nv_bfloat162* hp = reinterpret_cast<__nv_bfloat162*>(h + i);
    __nv_bfloat162* lp = reinterpret_cast<__nv_bfloat162*>(l + i);
    hp[0] = __halves2bfloat162(h0, h1);
    hp[1] = __halves2bfloat162(h2, h3);
    lp[0] = __halves2bfloat162(l0, l1);
    lp[1] = __halves2bfloat162(l2, l3);
}

// W[K][N] fp32  ->  Th/Tl [N][K] bf16 (transposed split)
__global__ __launch_bounds__(256) void trans_split_kernel(
    const float* __restrict__ W, __nv_bfloat16* __restrict__ Th,
    __nv_bfloat16* __restrict__ Tl, int K, int N)
{
    __shared__ float t[32][33];
    int n0 = blockIdx.x * 32, k0 = blockIdx.y * 32;
    int tx = threadIdx.x & 31, ty = threadIdx.x >> 5;  // ty 0..7
#pragma unroll
    for (int i = 0; i < 32; i += 8)
        t[ty + i][tx] = W[(size_t)(k0 + ty + i) * N + n0 + tx];
    __syncthreads();
#pragma unroll
    for (int i = 0; i < 32; i += 8) {
        float v = t[tx][ty + i];
        __nv_bfloat16 hh = __float2bfloat16(v);
        __nv_bfloat16 ll = __float2bfloat16(v - __bfloat162float(hh));
        size_t o = (size_t)(n0 + ty + i) * K + k0 + tx;
        Th[o] = hh;
        Tl[o] = ll;
    }
}

// ---------------- mma.sync bf16x3 GEMM:  C = (Ah+Al) @ (Bh+Bl)^T + bias ----------------
// A: [M,K] bf16 row-major (hi/lo). B: [N,K] bf16 row-major (hi/lo). C: [M,N] fp32.
// CTA tile 128x128, BK=32, 8 warps (4M x 2N -> 32x64 warp tiles), cp.async 2-stage.
#define LDS_EL 40     // smem row stride in bf16 elements (32 data + 8 pad); 80 bytes
#define OP_BYTES 10240            // 128 * 40 * 2
#define STAGE_BYTES (4 * OP_BYTES)

__global__ __launch_bounds__(256, 2) void gemm_mma(
    const __nv_bfloat16* __restrict__ Ah, const __nv_bfloat16* __restrict__ Al,
    const __nv_bfloat16* __restrict__ Bh, const __nv_bfloat16* __restrict__ Bl,
    const float* __restrict__ bias, float* __restrict__ C,
    int M, int N, int K)
{
    extern __shared__ char dsm[];
    const uint32_t sb = smem_u32(dsm);
    const int tid = threadIdx.x;
    const int lane = tid & 31;
    const int wid = tid >> 5;
    const int wm = wid & 3;            // 4 warps along M (32 rows each)
    const int wn = wid >> 2;           // 2 warps along N (64 cols each)
    const int rowBase = blockIdx.y * 128;
    const int colBase = blockIdx.x * 128;

    float acc[2][8][4];
#pragma unroll
    for (int i = 0; i < 2; i++)
#pragma unroll
        for (int j = 0; j < 8; j++)
#pragma unroll
            for (int c = 0; c < 4; c++) acc[i][j][c] = 0.0f;

    const int lr = tid >> 2;           // 0..63
    const int lc = tid & 3;            // 0..3 (16B chunk)

    // ---- stage loader: 128 rows x 32 bf16 per operand, 16B chunks ----
    auto load_stage = [&](int kc, int buf) {
        const int k0 = kc << 5;
        const uint32_t base = sb + (uint32_t)buf * STAGE_BYTES;
#pragma unroll
        for (int it = 0; it < 2; it++) {
            int row = it * 64 + lr;
            uint32_t so = (uint32_t)(row * LDS_EL + lc * 8) * 2;
            size_t ga = (size_t)(rowBase + row) * K + k0 + lc * 8;
            size_t gb = (size_t)(colBase + row) * K + k0 + lc * 8;
            cpa16(base + so,                Ah + ga);
            cpa16(base + OP_BYTES + so,     Al + ga);
            cpa16(base + 2 * OP_BYTES + so, Bh + gb);
            cpa16(base + 3 * OP_BYTES + so, Bl + gb);
        }
        CP_COMMIT();
    };

    auto compute_stage = [&](int buf) {
        const uint32_t base = sb + (uint32_t)buf * STAGE_BYTES;
#pragma unroll
        for (int ks = 0; ks < 2; ks++) {
            const int kcol = ks * 16;
            uint32_t ah[2][4], al[2][4];
#pragma unroll
            for (int mi = 0; mi < 2; mi++) {
                uint32_t off = (uint32_t)((wm * 32 + mi * 16 + (lane & 15)) * LDS_EL
                                          + kcol + (lane >> 4) * 8) * 2;
                ldm_x4(ah[mi], base + off);
                ldm_x4(al[mi], base + OP_BYTES + off);
            }
#pragma unroll
            for (int ni = 0; ni < 8; ni++) {
                uint32_t boff = (uint32_t)((wn * 64 + ni * 8 + (lane & 7)) * LDS_EL
                                           + kcol + ((lane >> 3) & 1) * 8) * 2;
                uint32_t bh0, bh1, bl0, bl1;
                ldm_x2(bh0, bh1, base + 2 * OP_BYTES + boff);
                ldm_x2(bl0, bl1, base + 3 * OP_BYTES + boff);
#pragma unroll
                for (int mi = 0; mi < 2; mi++) {
                    mma16816(acc[mi][ni], ah[mi], bh0, bh1);
                    mma16816(acc[mi][ni], al[mi], bh0, bh1);
                    mma16816(acc[mi][ni], ah[mi], bl0, bl1);
                }
            }
        }
    };

    const int nK = K >> 5;
    load_stage(0, 0);
    for (int kc = 0; kc < nK; kc++) {
        const int buf = kc & 1;
        if (kc + 1 < nK) {
            load_stage(kc + 1, buf ^ 1);
            CP_WAIT(1);
        } else {
            CP_WAIT(0);
        }
        __syncthreads();
        compute_stage(buf);
        __syncthreads();
    }

    // ---- epilogue: + bias, fp32 store ----
#pragma unroll
    for (int mi = 0; mi < 2; mi++) {
        int row0 = rowBase + wm * 32 + mi * 16 + (lane >> 2);
#pragma unroll
        for (int ni = 0; ni < 8; ni++) {
            int col = colBase + wn * 64 + ni * 8 + (lane & 3) * 2;
            float2 bv = *reinterpret_cast<const float2*>(&bias[col]);
            float2 r0, r1;
            r0.x = acc[mi][ni][0] + bv.x;
            r0.y = acc[mi][ni][1] + bv.y;
            r1.x = acc[mi][ni][2] + bv.x;
            r1.y = acc[mi][ni][3] + bv.y;
            *reinterpret_cast<float2*>(&C[(size_t)row0 * N + col]) = r0;
            *reinterpret_cast<float2*>(&C[(size_t)(row0 + 8) * N + col]) = r1;
        }
    }
}

// ------------- fused RMSNorm(q,k over D) + RoPE + head-layout scatter -------------
__global__ __launch_bounds__(256) void rms_rope_kernel(
    const float* __restrict__ cosT, const float* __restrict__ sinT,
    const float* __restrict__ q_scale, const float* __restrict__ k_scale)
{
    const int row = blockIdx.x;
    const int b = row / NSEQ;
    const int n = row % NSEQ;
    const float* qr = g_qkv + (size_t)row * 3 * DMODEL;
    const float* kr = qr + DMODEL;
    const float* vr = qr + 2 * DMODEL;

    float sq = 0.0f, sk = 0.0f;
    for (int i = threadIdx.x * 4; i < DMODEL; i += 256 * 4) {
        float4 q4 = *reinterpret_cast<const float4*>(&qr[i]);
        float4 k4 = *reinterpret_cast<const float4*>(&kr[i]);
        sq += q4.x * q4.x + q4.y * q4.y + q4.z * q4.z + q4.w * q4.w;
        sk += k4.x * k4.x + k4.y * k4.y + k4.z * k4.z + k4.w * k4.w;
    }
#pragma unroll
    for (int off = 16; off >= 1; off >>= 1) {
        sq += __shfl_xor_sync(0xffffffffu, sq, off);
        sk += __shfl_xor_sync(0xffffffffu, sk, off);
    }
    __shared__ float wq[8], wk[8];
    __shared__ float s_iq, s_ik;
    int wid = threadIdx.x >> 5, lid = threadIdx.x & 31;
    if (lid == 0) { wq[wid] = sq; wk[wid] = sk; }
    __syncthreads();
    if (threadIdx.x == 0) {
        float a = 0.0f, c = 0.0f;
#pragma unroll
        for (int w = 0; w < 8; w++) { a += wq[w]; c += wk[w]; }
        s_iq = rsqrtf(a / (float)DMODEL + 1e-6f);
        s_ik = rsqrtf(c / (float)DMODEL + 1e-6f);
    }
    __syncthreads();
    const float iq = s_iq, ik = s_ik;

    for (int p = threadIdx.x; p < DMODEL / 2; p += 256) {
        int h = p >> 5;
        int j = p & 31;
        int i0 = h * HD + 2 * j;
        float c = cosT[n * 32 + j];
        float s = sinT[n * 32 + j];
        float q0 = qr[i0]     * iq * q_scale[i0];
        float q1 = qr[i0 + 1] * iq * q_scale[i0 + 1];
        float k0 = kr[i0]     * ik * k_scale[i0];
        float k1 = kr[i0 + 1] * ik * k_scale[i0 + 1];
        size_t base = (((size_t)b * NH + h) * NSEQ + n) * HD + 2 * j;
        g_q[base]     = q0 * c - q1 * s;
        g_q[base + 1] = q0 * s + q1 * c;
        g_k[base]     = k0 * c - k1 * s;
        g_k[base + 1] = k0 * s + k1 * c;
    }
    for (int i = threadIdx.x * 4; i < DMODEL; i += 1024) {
        float4 v4 = *reinterpret_cast<const float4*>(&vr[i]);
        int h = i >> 6;
        int c = i & 63;
        *reinterpret_cast<float4*>(
            &g_v[(((size_t)b * NH + h) * NSEQ + n) * HD + c]) = v4;
    }
}

// ---------------- FlashAttention-2 style fp32 attention ----------------
__global__ __launch_bounds__(256) void attn_kernel()
{
    extern __shared__ float sm[];
    float* Qt = sm;
    float* Kt = Qt + 64 * 128;
    float* Vs = Kt + 64 * 128;
    float* Ss = Vs + 128 * 64;

    const int tid = threadIdx.x;
    const int tx = tid & 15;
    const int ty = tid >> 4;
    const int h = blockIdx.y, b = blockIdx.z;
    const size_t bhBase = ((size_t)b * NH + h) * (size_t)NSEQ * HD;
    const float* Qg = g_q + bhBase + (size_t)blockIdx.x * 128 * HD;
    const float* Kg = g_k + bhBase;
    const float* Vg = g_v + bhBase;
    const float scale = 0.125f;

#pragma unroll
    for (int it = 0; it < 8; it++) {
        int idx = it * 256 + tid;
        int r = idx >> 4;
        int c = (idx & 15) << 2;
        float4 v = *reinterpret_cast<const float4*>(&Qg[r * HD + c]);
        Qt[(c + 0) * 128 + r] = v.x * scale;
        Qt[(c + 1) * 128 + r] = v.y * scale;
        Qt[(c + 2) * 128 + r] = v.z * scale;
        Qt[(c + 3) * 128 + r] = v.w * scale;
    }

    float m[8], l[8], o[8][4];
#pragma unroll
    for (int i = 0; i < 8; i++) {
        m[i] = -3.402823466e38f;
        l[i] = 0.0f;
#pragma unroll
        for (int c = 0; c < 4; c++) o[i][c] = 0.0f;
    }

    for (int kt = 0; kt < NSEQ / 128; kt++) {
        __syncthreads();
        const float* Kgt = Kg + (size_t)kt * 128 * HD;
        const float* Vgt = Vg + (size_t)kt * 128 * HD;
#pragma unroll
        for (int it = 0; it < 8; it++) {
            int idx = it * 256 + tid;
            int r = idx >> 4;
            int c = (idx & 15) << 2;
            float4 kv = *reinterpret_cast<const float4*>(&Kgt[r * HD + c]);
            Kt[(c + 0) * 128 + r] = kv.x;
            Kt[(c + 1) * 128 + r] = kv.y;
            Kt[(c + 2) * 128 + r] = kv.z;
            Kt[(c + 3) * 128 + r] = kv.w;
            float4 vv = *reinterpret_cast<const float4*>(&Vgt[r * HD + c]);
            *reinterpret_cast<float4*>(&Vs[r * HD + c]) = vv;
        }
        __syncthreads();

        float s[8][8];
#pragma unroll
        for (int i = 0; i < 8; i++)
#pragma unroll
            for (int j = 0; j < 8; j++) s[i][j] = 0.0f;

#pragma unroll 4
        for (int c = 0; c < HD; c++) {
            float a[8], bb[8];
            *reinterpret_cast<float4*>(&a[0])  = *reinterpret_cast<float4*>(&Qt[c * 128 + ty * 8]);
            *reinterpret_cast<float4*>(&a[4])  = *reinterpret_cast<float4*>(&Qt[c * 128 + ty * 8 + 4]);
            *reinterpret_cast<float4*>(&bb[0]) = *reinterpret_cast<float4*>(&Kt[c * 128 + tx * 8]);
            *reinterpret_cast<float4*>(&bb[4]) = *reinterpret_cast<float4*>(&Kt[c * 128 + tx * 8 + 4]);
#pragma unroll
            for (int i = 0; i < 8; i++)
#pragma unroll
                for (int j = 0; j < 8; j++)
                    s[i][j] += a[i] * bb[j];
        }

#pragma unroll
        for (int i = 0; i < 8; i++) {
            float mt = s[i][0];
#pragma unroll
            for (int j = 1; j < 8; j++) mt = fmaxf(mt, s[i][j]);
#pragma unroll
            for (int off = 8; off >= 1; off >>= 1)
                mt = fmaxf(mt, __shfl_xor_sync(0xffffffffu, mt, off));
            float mn = fmaxf(m[i], mt);
            float alpha = __expf(m[i] - mn);
            m[i] = mn;
            float ls = 0.0f;
#pragma unroll
            for (int j = 0; j < 8; j++) {
                float p = __expf(s[i][j] - mn);
                s[i][j] = p;
                ls += p;
            }
#pragma unroll
            for (int off = 8; off >= 1; off >>= 1)
                ls += __shfl_xor_sync(0xffffffffu, ls, off);
            l[i] = l[i] * alpha + ls;
#pragma unroll
            for (int c = 0; c < 4; c++) o[i][c] *= alpha;
            *reinterpret_cast<float4*>(&Ss[(ty * 8 + i) * 128 + tx * 8]) =
                make_float4(s[i][0], s[i][1], s[i][2], s[i][3]);
            *reinterpret_cast<float4*>(&Ss[(ty * 8 + i) * 128 + tx * 8 + 4]) =
                make_float4(s[i][4], s[i][5], s[i][6], s[i][7]);
        }
        __syncthreads();

#pragma unroll 2
        for (int j = 0; j < 128; j += 4) {
            float4 v0 = *reinterpret_cast<float4*>(&Vs[(j + 0) * HD + tx * 4]);
            float4 v1 = *reinterpret_cast<float4*>(&Vs[(j + 1) * HD + tx * 4]);
            float4 v2 = *reinterpret_cast<float4*>(&Vs[(j + 2) * HD + tx * 4]);
            float4 v3 = *reinterpret_cast<float4*>(&Vs[(j + 3) * HD + tx * 4]);
#pragma unroll
            for (int i = 0; i < 8; i++) {
                float4 p = *reinterpret_cast<float4*>(&Ss[(ty * 8 + i) * 128 + j]);
                o[i][0] += p.x * v0.x + p.y * v1.x + p.z * v2.x + p.w * v3.x;
                o[i][1] += p.x * v0.y + p.y * v1.y + p.z * v2.y + p.w * v3.y;
                o[i][2] += p.x * v0.z + p.y * v1.z + p.z * v2.z + p.w * v3.z;
                o[i][3] += p.x * v0.w + p.y * v1.w + p.z * v2.w + p.w * v3.w;
            }
        }
    }

#pragma unroll
    for (int i = 0; i < 8; i++) {
        float inv = 1.0f / l[i];
        int q = blockIdx.x * 128 + ty * 8 + i;
        size_t row = (size_t)b * NSEQ + q;
        float4 r = make_float4(o[i][0] * inv, o[i][1] * inv, o[i][2] * inv, o[i][3] * inv);
        *reinterpret_cast<float4*>(&g_o[row * DMODEL + h * HD + tx * 4]) = r;
    }
}

// ---------------- launch ----------------
extern "C" void kernel_launch(void* const* d_in, const int* in_sizes, int n_in,
                              void* d_out, int out_size)
{
    const float* x       = (const float*)d_in[0];
    const float* cosT    = (const float*)d_in[1];
    const float* sinT    = (const float*)d_in[2];
    const float* Wqkv    = (const float*)d_in[3];
    const float* bqkv    = (const float*)d_in[4];
    const float* q_scale = (const float*)d_in[5];
    const float* k_scale = (const float*)d_in[6];
    const float* Wout    = (const float*)d_in[7];
    const float* bout    = (const float*)d_in[8];
    float* out = (float*)d_out;

    float *qkv_p, *o_p;
    __nv_bfloat16 *xh_p, *xl_p, *oh_p, *ol_p, *wqh_p, *wql_p, *woh_p, *wol_p;
    cudaGetSymbolAddress((void**)&qkv_p, g_qkv);
    cudaGetSymbolAddress((void**)&o_p, g_o);
    cudaGetSymbolAddress((void**)&xh_p, g_xh);
    cudaGetSymbolAddress((void**)&xl_p, g_xl);
    cudaGetSymbolAddress((void**)&oh_p, g_oh);
    cudaGetSymbolAddress((void**)&ol_p, g_ol);
    cudaGetSymbolAddress((void**)&wqh_p, g_wqh);
    cudaGetSymbolAddress((void**)&wql_p, g_wql);
    cudaGetSymbolAddress((void**)&woh_p, g_woh);
    cudaGetSymbolAddress((void**)&wol_p, g_wol);

    const int gemm_smem = 2 * STAGE_BYTES;   // 81920
    cudaFuncSetAttribute(gemm_mma, cudaFuncAttributeMaxDynamicSharedMemorySize, gemm_smem);
    const int attn_smem = (64 * 128 + 64 * 128 + 128 * 64 + 128 * 128) * 4;
    cudaFuncSetAttribute(attn_kernel, cudaFuncAttributeMaxDynamicSharedMemorySize, attn_smem);

    // 0) splits
    split_kernel<<<(MROWS * DMODEL) / 1024, 256>>>(x, xh_p, xl_p, MROWS * DMODEL);
    trans_split_kernel<<<dim3(3 * DMODEL / 32, DMODEL / 32), 256>>>(
        Wqkv, wqh_p, wql_p, DMODEL, 3 * DMODEL);
    trans_split_kernel<<<dim3(DMODEL / 32, DMODEL / 32), 256>>>(
        Wout, woh_p, wol_p, DMODEL, DMODEL);

    // 1) QKV GEMM (mma.sync bf16x3): [4096,1024] @ [1024,3072] + bqkv
    gemm_mma<<<dim3(3 * DMODEL / 128, MROWS / 128), 256, gemm_smem>>>(
        xh_p, xl_p, wqh_p, wql_p, bqkv, qkv_p, MROWS, 3 * DMODEL, DMODEL);

    // 2) RMSNorm + RoPE + layout
    rms_rope_kernel<<<MROWS, 256>>>(cosT, sinT, q_scale, k_scale);

    // 3) Attention (fp32)
    attn_kernel<<<dim3(NSEQ / 128, NH, B_SZ), 256, attn_smem>>>();

    // 4) split attention output, then out-proj GEMM
    split_kernel<<<(MROWS * DMODEL) / 1024, 256>>>(o_p, oh_p, ol_p, MROWS * DMODEL);
    gemm_mma<<<dim3(DMODEL / 128, MROWS / 128), 256, gemm_smem>>>(
        oh_p, ol_p, woh_p, wol_p, bout, out, MROWS, DMODEL, DMODEL);
}

// round 5
// speedup vs baseline: 2.7320x; 2.0050x over previous
#include <cuda_runtime.h>
#include <cuda_bf16.h>
#include <cstdint>
#include <math.h>

#define B_SZ 2
#define NSEQ 2048
#define DMODEL 1024
#define NH 16
#define HD 64
#define MROWS (B_SZ * NSEQ)   // 4096

// ---------------- scratch (static device globals; no allocation) ----------------
__device__ float g_qkv[(size_t)MROWS * 3 * DMODEL];

// split bf16 q/k/v in [B,H,N,64]
__device__ __nv_bfloat16 g_qh[(size_t)B_SZ * NH * NSEQ * HD];
__device__ __nv_bfloat16 g_ql[(size_t)B_SZ * NH * NSEQ * HD];
__device__ __nv_bfloat16 g_kh[(size_t)B_SZ * NH * NSEQ * HD];
__device__ __nv_bfloat16 g_kl[(size_t)B_SZ * NH * NSEQ * HD];
__device__ __nv_bfloat16 g_vh[(size_t)B_SZ * NH * NSEQ * HD];
__device__ __nv_bfloat16 g_vl[(size_t)B_SZ * NH * NSEQ * HD];

// bf16 split GEMM operands
__device__ __nv_bfloat16 g_xh[(size_t)MROWS * DMODEL];
__device__ __nv_bfloat16 g_xl[(size_t)MROWS * DMODEL];
__device__ __nv_bfloat16 g_oh[(size_t)MROWS * DMODEL];
__device__ __nv_bfloat16 g_ol[(size_t)MROWS * DMODEL];
__device__ __nv_bfloat16 g_wqh[(size_t)3 * DMODEL * DMODEL];  // Wqkv^T
__device__ __nv_bfloat16 g_wql[(size_t)3 * DMODEL * DMODEL];
__device__ __nv_bfloat16 g_woh[(size_t)DMODEL * DMODEL];      // Wout^T
__device__ __nv_bfloat16 g_wol[(size_t)DMODEL * DMODEL];

// ---------------- helpers (base sm_100-safe) ----------------
__device__ __forceinline__ uint32_t smem_u32(const void* p) {
    uint32_t a;
    asm("{ .reg .u64 t; cvta.to.shared.u64 t, %1; cvt.u32.u64 %0, t; }"
        : "=r"(a) : "l"(p));
    return a;
}
__device__ __forceinline__ void cpa16(uint32_t s, const void* g) {
    asm volatile("cp.async.cg.shared.global [%0], [%1], 16;" :: "r"(s), "l"(g));
}
#define CP_COMMIT() asm volatile("cp.async.commit_group;" ::: "memory")
#define CP_WAIT(n)  asm volatile("cp.async.wait_group %0;" :: "n"(n) : "memory")

__device__ __forceinline__ void ldm_x4(uint32_t* r, uint32_t addr) {
    asm volatile("ldmatrix.sync.aligned.m8n8.x4.shared.b16 {%0,%1,%2,%3}, [%4];"
        : "=r"(r[0]), "=r"(r[1]), "=r"(r[2]), "=r"(r[3]) : "r"(addr));
}
__device__ __forceinline__ void ldm_x4_t(uint32_t* r, uint32_t addr) {
    asm volatile("ldmatrix.sync.aligned.m8n8.x4.trans.shared.b16 {%0,%1,%2,%3}, [%4];"
        : "=r"(r[0]), "=r"(r[1]), "=r"(r[2]), "=r"(r[3]) : "r"(addr));
}
__device__ __forceinline__ void ldm_x2(uint32_t& r0, uint32_t& r1, uint32_t addr) {
    asm volatile("ldmatrix.sync.aligned.m8n8.x2.shared.b16 {%0,%1}, [%2];"
        : "=r"(r0), "=r"(r1) : "r"(addr));
}
__device__ __forceinline__ void mma16816(float* d, const uint32_t* a,
                                         uint32_t b0, uint32_t b1) {
    asm volatile(
        "mma.sync.aligned.m16n8k16.row.col.f32.bf16.bf16.f32 "
        "{%0,%1,%2,%3}, {%4,%5,%6,%7}, {%8,%9}, {%0,%1,%2,%3};"
        : "+f"(d[0]), "+f"(d[1]), "+f"(d[2]), "+f"(d[3])
        : "r"(a[0]), "r"(a[1]), "r"(a[2]), "r"(a[3]), "r"(b0), "r"(b1));
}

// FFMA-only exp (avoids MUFU bottleneck: rt_SMSP=8 -> 0.5 MUFU/cyc/SM)
__device__ __forceinline__ float fexp(float x) {
    x = fmaxf(x, -80.0f);
    float t = x * 1.4426950408889634f;
    float fm = t + 12582912.0f;                 // round-to-nearest via magic
    int ii = __float_as_int(fm) << 23;
    float f = t - (fm - 12582912.0f);           // frac in [-0.5, 0.5]
    float p = 1.33335581e-3f;
    p = fmaf(p, f, 9.61812911e-3f);
    p = fmaf(p, f, 5.55041087e-2f);
    p = fmaf(p, f, 2.40226507e-1f);
    p = fmaf(p, f, 6.93147181e-1f);
    p = fmaf(p, f, 1.0f);
    return __int_as_float(__float_as_int(p) + ii);
}
__device__ __forceinline__ uint32_t packbf(float a, float b) {
    __nv_bfloat162 t = __halves2bfloat162(__float2bfloat16(a), __float2bfloat16(b));
    return *reinterpret_cast<uint32_t*>(&t);
}

// ---------------- split kernels ----------------
__global__ __launch_bounds__(256) void split_kernel(
    const float* __restrict__ s, __nv_bfloat16* __restrict__ h,
    __nv_bfloat16* __restrict__ l, int n)
{
    int i = (blockIdx.x * 256 + threadIdx.x) * 4;
    if (i >= n) return;
    float4 v = *reinterpret_cast<const float4*>(s + i);
    __nv_bfloat16 h0 = __float2bfloat16(v.x), h1 = __float2bfloat16(v.y);
    __nv_bfloat16 h2 = __float2bfloat16(v.z), h3 = __float2bfloat16(v.w);
    __nv_bfloat16 l0 = __float2bfloat16(v.x - __bfloat162float(h0));
    __nv_bfloat16 l1 = __float2bfloat16(v.y - __bfloat162float(h1));
    __nv_bfloat16 l2 = __float2bfloat16(v.z - __bfloat162float(h2));
    __nv_bfloat16 l3 = __float2bfloat16(v.w - __bfloat162float(h3));
    __nv_bfloat162* hp = reinterpret_cast<__nv_bfloat162*>(h + i);
    __nv_bfloat162* lp = reinterpret_cast<__nv_bfloat162*>(l + i);
    hp[0] = __halves2bfloat162(h0, h1);
    hp[1] = __halves2bfloat162(h2, h3);
    lp[0] = __halves2bfloat162(l0, l1);
    lp[1] = __halves2bfloat162(l2, l3);
}

// W[K][N] fp32  ->  Th/Tl [N][K] bf16 (transposed split)
__global__ __launch_bounds__(256) void trans_split_kernel(
    const float* __restrict__ W, __nv_bfloat16* __restrict__ Th,
    __nv_bfloat16* __restrict__ Tl, int K, int N)
{
    __shared__ float t[32][33];
    int n0 = blockIdx.x * 32, k0 = blockIdx.y * 32;
    int tx = threadIdx.x & 31, ty = threadIdx.x >> 5;
#pragma unroll
    for (int i = 0; i < 32; i += 8)
        t[ty + i][tx] = W[(size_t)(k0 + ty + i) * N + n0 + tx];
    __syncthreads();
#pragma unroll
    for (int i = 0; i < 32; i += 8) {
        float v = t[tx][ty + i];
        __nv_bfloat16 hh = __float2bfloat16(v);
        __nv_bfloat16 ll = __float2bfloat16(v - __bfloat162float(hh));
        size_t o = (size_t)(n0 + ty + i) * K + k0 + tx;
        Th[o] = hh;
        Tl[o] = ll;
    }
}

// ---------------- mma.sync bf16x3 GEMM (unchanged from R4) ----------------
#define LDS_EL 40
#define OP_BYTES 10240
#define STAGE_BYTES (4 * OP_BYTES)

__global__ __launch_bounds__(256, 2) void gemm_mma(
    const __nv_bfloat16* __restrict__ Ah, const __nv_bfloat16* __restrict__ Al,
    const __nv_bfloat16* __restrict__ Bh, const __nv_bfloat16* __restrict__ Bl,
    const float* __restrict__ bias, float* __restrict__ C,
    int M, int N, int K)
{
    extern __shared__ char dsm[];
    const uint32_t sb = smem_u32(dsm);
    const int tid = threadIdx.x;
    const int lane = tid & 31;
    const int wid = tid >> 5;
    const int wm = wid & 3;
    const int wn = wid >> 2;
    const int rowBase = blockIdx.y * 128;
    const int colBase = blockIdx.x * 128;

    float acc[2][8][4];
#pragma unroll
    for (int i = 0; i < 2; i++)
#pragma unroll
        for (int j = 0; j < 8; j++)
#pragma unroll
            for (int c = 0; c < 4; c++) acc[i][j][c] = 0.0f;

    const int lr = tid >> 2;
    const int lc = tid & 3;

    auto load_stage = [&](int kc, int buf) {
        const int k0 = kc << 5;
        const uint32_t base = sb + (uint32_t)buf * STAGE_BYTES;
#pragma unroll
        for (int it = 0; it < 2; it++) {
            int row = it * 64 + lr;
            uint32_t so = (uint32_t)(row * LDS_EL + lc * 8) * 2;
            size_t ga = (size_t)(rowBase + row) * K + k0 + lc * 8;
            size_t gb = (size_t)(colBase + row) * K + k0 + lc * 8;
            cpa16(base + so,                Ah + ga);
            cpa16(base + OP_BYTES + so,     Al + ga);
            cpa16(base + 2 * OP_BYTES + so, Bh + gb);
            cpa16(base + 3 * OP_BYTES + so, Bl + gb);
        }
        CP_COMMIT();
    };

    auto compute_stage = [&](int buf) {
        const uint32_t base = sb + (uint32_t)buf * STAGE_BYTES;
#pragma unroll
        for (int ks = 0; ks < 2; ks++) {
            const int kcol = ks * 16;
            uint32_t ah[2][4], al[2][4];
#pragma unroll
            for (int mi = 0; mi < 2; mi++) {
                uint32_t off = (uint32_t)((wm * 32 + mi * 16 + (lane & 15)) * LDS_EL
                                          + kcol + (lane >> 4) * 8) * 2;
                ldm_x4(ah[mi], base + off);
                ldm_x4(al[mi], base + OP_BYTES + off);
            }
#pragma unroll
            for (int ni = 0; ni < 8; ni++) {
                uint32_t boff = (uint32_t)((wn * 64 + ni * 8 + (lane & 7)) * LDS_EL
                                           + kcol + ((lane >> 3) & 1) * 8) * 2;
                uint32_t bh0, bh1, bl0, bl1;
                ldm_x2(bh0, bh1, base + 2 * OP_BYTES + boff);
                ldm_x2(bl0, bl1, base + 3 * OP_BYTES + boff);
#pragma unroll
                for (int mi = 0; mi < 2; mi++) {
                    mma16816(acc[mi][ni], ah[mi], bh0, bh1);
                    mma16816(acc[mi][ni], al[mi], bh0, bh1);
                    mma16816(acc[mi][ni], ah[mi], bl0, bl1);
                }
            }
        }
    };

    const int nK = K >> 5;
    load_stage(0, 0);
    for (int kc = 0; kc < nK; kc++) {
        const int buf = kc & 1;
        if (kc + 1 < nK) {
            load_stage(kc + 1, buf ^ 1);
            CP_WAIT(1);
        } else {
            CP_WAIT(0);
        }
        __syncthreads();
        compute_stage(buf);
        __syncthreads();
    }

#pragma unroll
    for (int mi = 0; mi < 2; mi++) {
        int row0 = rowBase + wm * 32 + mi * 16 + (lane >> 2);
#pragma unroll
        for (int ni = 0; ni < 8; ni++) {
            int col = colBase + wn * 64 + ni * 8 + (lane & 3) * 2;
            float2 bv = *reinterpret_cast<const float2*>(&bias[col]);
            float2 r0, r1;
            r0.x = acc[mi][ni][0] + bv.x;
            r0.y = acc[mi][ni][1] + bv.y;
            r1.x = acc[mi][ni][2] + bv.x;
            r1.y = acc[mi][ni][3] + bv.y;
            *reinterpret_cast<float2*>(&C[(size_t)row0 * N + col]) = r0;
            *reinterpret_cast<float2*>(&C[(size_t)(row0 + 8) * N + col]) = r1;
        }
    }
}

// ------------- fused RMSNorm + RoPE + split-bf16 head-layout scatter -------------
// q pre-scaled by 1/8 (softmax scale) before splitting.
__global__ __launch_bounds__(256) void rms_rope_kernel(
    const float* __restrict__ cosT, const float* __restrict__ sinT,
    const float* __restrict__ q_scale, const float* __restrict__ k_scale)
{
    const int row = blockIdx.x;
    const int b = row / NSEQ;
    const int n = row % NSEQ;
    const float* qr = g_qkv + (size_t)row * 3 * DMODEL;
    const float* kr = qr + DMODEL;
    const float* vr = qr + 2 * DMODEL;

    float sq = 0.0f, sk = 0.0f;
    for (int i = threadIdx.x * 4; i < DMODEL; i += 256 * 4) {
        float4 q4 = *reinterpret_cast<const float4*>(&qr[i]);
        float4 k4 = *reinterpret_cast<const float4*>(&kr[i]);
        sq += q4.x * q4.x + q4.y * q4.y + q4.z * q4.z + q4.w * q4.w;
        sk += k4.x * k4.x + k4.y * k4.y + k4.z * k4.z + k4.w * k4.w;
    }
#pragma unroll
    for (int off = 16; off >= 1; off >>= 1) {
        sq += __shfl_xor_sync(0xffffffffu, sq, off);
        sk += __shfl_xor_sync(0xffffffffu, sk, off);
    }
    __shared__ float wq[8], wk[8];
    __shared__ float s_iq, s_ik;
    int wid = threadIdx.x >> 5, lid = threadIdx.x & 31;
    if (lid == 0) { wq[wid] = sq; wk[wid] = sk; }
    __syncthreads();
    if (threadIdx.x == 0) {
        float a = 0.0f, c = 0.0f;
#pragma unroll
        for (int w = 0; w < 8; w++) { a += wq[w]; c += wk[w]; }
        s_iq = rsqrtf(a / (float)DMODEL + 1e-6f);
        s_ik = rsqrtf(c / (float)DMODEL + 1e-6f);
    }
    __syncthreads();
    const float iq = s_iq, ik = s_ik;

    for (int p = threadIdx.x; p < DMODEL / 2; p += 256) {
        int h = p >> 5;
        int j = p & 31;
        int i0 = h * HD + 2 * j;
        float c = cosT[n * 32 + j];
        float s = sinT[n * 32 + j];
        float q0 = qr[i0]     * iq * q_scale[i0];
        float q1 = qr[i0 + 1] * iq * q_scale[i0 + 1];
        float k0 = kr[i0]     * ik * k_scale[i0];
        float k1 = kr[i0 + 1] * ik * k_scale[i0 + 1];
        float q0r = (q0 * c - q1 * s) * 0.125f;
        float q1r = (q0 * s + q1 * c) * 0.125f;
        float k0r = k0 * c - k1 * s;
        float k1r = k0 * s + k1 * c;
        size_t base = (((size_t)b * NH + h) * NSEQ + n) * HD + 2 * j;
        __nv_bfloat16 qh0 = __float2bfloat16(q0r), qh1 = __float2bfloat16(q1r);
        __nv_bfloat16 kh0 = __float2bfloat16(k0r), kh1 = __float2bfloat16(k1r);
        *reinterpret_cast<__nv_bfloat162*>(&g_qh[base]) = __halves2bfloat162(qh0, qh1);
        *reinterpret_cast<__nv_bfloat162*>(&g_ql[base]) = __halves2bfloat162(
            __float2bfloat16(q0r - __bfloat162float(qh0)),
            __float2bfloat16(q1r - __bfloat162float(qh1)));
        *reinterpret_cast<__nv_bfloat162*>(&g_kh[base]) = __halves2bfloat162(kh0, kh1);
        *reinterpret_cast<__nv_bfloat162*>(&g_kl[base]) = __halves2bfloat162(
            __float2bfloat16(k0r - __bfloat162float(kh0)),
            __float2bfloat16(k1r - __bfloat162float(kh1)));
    }
    for (int i = threadIdx.x * 4; i < DMODEL; i += 1024) {
        float4 v4 = *reinterpret_cast<const float4*>(&vr[i]);
        int h = i >> 6;
        int c = i & 63;
        size_t base = (((size_t)b * NH + h) * NSEQ + n) * HD + c;
        __nv_bfloat16 h0 = __float2bfloat16(v4.x), h1 = __float2bfloat16(v4.y);
        __nv_bfloat16 h2 = __float2bfloat16(v4.z), h3 = __float2bfloat16(v4.w);
        *reinterpret_cast<__nv_bfloat162*>(&g_vh[base])     = __halves2bfloat162(h0, h1);
        *reinterpret_cast<__nv_bfloat162*>(&g_vh[base + 2]) = __halves2bfloat162(h2, h3);
        *reinterpret_cast<__nv_bfloat162*>(&g_vl[base])     = __halves2bfloat162(
            __float2bfloat16(v4.x - __bfloat162float(h0)),
            __float2bfloat16(v4.y - __bfloat162float(h1)));
        *reinterpret_cast<__nv_bfloat162*>(&g_vl[base + 2]) = __halves2bfloat162(
            __float2bfloat16(v4.z - __bfloat162float(h2)),
            __float2bfloat16(v4.w - __bfloat162float(h3)));
    }
}

// ---------------- FA2 attention with mma.sync bf16x3 ----------------
// grid (16, NH, B), 256 threads = 8 warps, each warp owns 16 q rows.
// smem: Qh,Ql [128][72]; 2 x {Kh,Kl,Vh,Vl} [128][72] double-buffered.
#define AT_STRIDE 72
#define AT_TILE 18432          // 128*72*2 bytes
#define KV_BASE  36864         // after Qh,Ql
#define KV_STAGE 73728         // 4 tiles

__global__ __launch_bounds__(256, 1) void attn_mma()
{
    extern __shared__ char att_sm[];
    const uint32_t sb = smem_u32(att_sm);
    const int tid = threadIdx.x;
    const int lane = tid & 31;
    const int wid = tid >> 5;
    const int h = blockIdx.y, b = blockIdx.z;
    const size_t bh = ((size_t)b * NH + h) * (size_t)NSEQ * HD;
    const size_t q0g = bh + (size_t)blockIdx.x * 128 * HD;

    // Q tiles (hi, lo)
#pragma unroll
    for (int it = 0; it < 4; it++) {
        int id = it * 256 + tid;
        int r = id >> 3, ch = id & 7;
        uint32_t so = (uint32_t)(r * 144 + ch * 16);
        size_t g = q0g + (size_t)r * HD + ch * 8;
        cpa16(sb + so,           g_qh + g);
        cpa16(sb + AT_TILE + so, g_ql + g);
    }
    CP_COMMIT();

    auto load_kv = [&](int kt, int buf) {
        const uint32_t base = sb + KV_BASE + (uint32_t)buf * KV_STAGE;
        size_t g0 = bh + (size_t)kt * 128 * HD;
#pragma unroll
        for (int it = 0; it < 4; it++) {
            int id = it * 256 + tid;
            int r = id >> 3, ch = id & 7;
            uint32_t so = (uint32_t)(r * 144 + ch * 16);
            size_t g = g0 + (size_t)r * HD + ch * 8;
            cpa16(base + so,               g_kh + g);
            cpa16(base + AT_TILE + so,     g_kl + g);
            cpa16(base + 2 * AT_TILE + so, g_vh + g);
            cpa16(base + 3 * AT_TILE + so, g_vl + g);
        }
        CP_COMMIT();
    };

    float m0 = -1e30f, m1 = -1e30f, l0 = 0.0f, l1 = 0.0f;
    float o[8][4];
#pragma unroll
    for (int i = 0; i < 8; i++)
#pragma unroll
        for (int c = 0; c < 4; c++) o[i][c] = 0.0f;

    load_kv(0, 0);

    for (int kt = 0; kt < NSEQ / 128; kt++) {
        const int buf = kt & 1;
        if (kt + 1 < NSEQ / 128) { load_kv(kt + 1, buf ^ 1); CP_WAIT(1); }
        else                     { CP_WAIT(0); }
        __syncthreads();

        const uint32_t kbase = sb + KV_BASE + (uint32_t)buf * KV_STAGE;

        // ---- S = (Q/8) K^T : 128x128 per CTA, 16x128 per warp ----
        float s[16][4];
#pragma unroll
        for (int i = 0; i < 16; i++)
#pragma unroll
            for (int c = 0; c < 4; c++) s[i][c] = 0.0f;

#pragma unroll
        for (int ks = 0; ks < 4; ks++) {
            uint32_t qoff = (uint32_t)((wid * 16 + (lane & 15)) * AT_STRIDE
                                       + ks * 16 + (lane >> 4) * 8) * 2;
            uint32_t ah[4], al[4];
            ldm_x4(ah, sb + qoff);
            ldm_x4(al, sb + AT_TILE + qoff);
#pragma unroll
            for (int nf2 = 0; nf2 < 8; nf2++) {
                uint32_t koff = (uint32_t)((nf2 * 16 + (lane & 15)) * AT_STRIDE
                                           + ks * 16 + (lane >> 4) * 8) * 2;
                uint32_t bh4[4], bl4[4];
                ldm_x4(bh4, kbase + koff);
                ldm_x4(bl4, kbase + AT_TILE + koff);
                mma16816(s[2 * nf2],     ah, bh4[0], bh4[2]);
                mma16816(s[2 * nf2],     al, bh4[0], bh4[2]);
                mma16816(s[2 * nf2],     ah, bl4[0], bl4[2]);
                mma16816(s[2 * nf2 + 1], ah, bh4[1], bh4[3]);
                mma16816(s[2 * nf2 + 1], al, bh4[1], bh4[3]);
                mma16816(s[2 * nf2 + 1], ah, bl4[1], bl4[3]);
            }
        }

        // ---- online softmax (rows r0=lane>>2, r1=r0+8 of warp tile) ----
        float mx0 = -1e30f, mx1 = -1e30f;
#pragma unroll
        for (int nf = 0; nf < 16; nf++) {
            mx0 = fmaxf(mx0, fmaxf(s[nf][0], s[nf][1]));
            mx1 = fmaxf(mx1, fmaxf(s[nf][2], s[nf][3]));
        }
        mx0 = fmaxf(mx0, __shfl_xor_sync(0xffffffffu, mx0, 1));
        mx0 = fmaxf(mx0, __shfl_xor_sync(0xffffffffu, mx0, 2));
        mx1 = fmaxf(mx1, __shfl_xor_sync(0xffffffffu, mx1, 1));
        mx1 = fmaxf(mx1, __shfl_xor_sync(0xffffffffu, mx1, 2));
        float mn0 = fmaxf(m0, mx0), mn1 = fmaxf(m1, mx1);
        float a0 = fexp(m0 - mn0), a1 = fexp(m1 - mn1);
        m0 = mn0; m1 = mn1;
#pragma unroll
        for (int nf = 0; nf < 8; nf++) {
            o[nf][0] *= a0; o[nf][1] *= a0;
            o[nf][2] *= a1; o[nf][3] *= a1;
        }

        // ---- exp + pack + PV, one k-step (16 keys) at a time ----
        const uint32_t vbase = kbase + 2 * AT_TILE;
        float sum0 = 0.0f, sum1 = 0.0f;
#pragma unroll
        for (int t = 0; t < 8; t++) {
            float p00 = fexp(s[2 * t][0] - mn0),     p01 = fexp(s[2 * t][1] - mn0);
            float p02 = fexp(s[2 * t][2] - mn1),     p03 = fexp(s[2 * t][3] - mn1);
            float p10 = fexp(s[2 * t + 1][0] - mn0), p11 = fexp(s[2 * t + 1][1] - mn0);
            float p12 = fexp(s[2 * t + 1][2] - mn1), p13 = fexp(s[2 * t + 1][3] - mn1);
            sum0 += (p00 + p01) + (p10 + p11);
            sum1 += (p02 + p03) + (p12 + p13);
            uint32_t ph[4], pl[4];
            ph[0] = packbf(p00, p01); ph[1] = packbf(p02, p03);
            ph[2] = packbf(p10, p11); ph[3] = packbf(p12, p13);
            {
                __nv_bfloat162* hp;
                hp = reinterpret_cast<__nv_bfloat162*>(&ph[0]);
                pl[0] = packbf(p00 - __bfloat162float(hp->x), p01 - __bfloat162float(hp->y));
                hp = reinterpret_cast<__nv_bfloat162*>(&ph[1]);
                pl[1] = packbf(p02 - __bfloat162float(hp->x), p03 - __bfloat162float(hp->y));
                hp = reinterpret_cast<__nv_bfloat162*>(&ph[2]);
                pl[2] = packbf(p10 - __bfloat162float(hp->x), p11 - __bfloat162float(hp->y));
                hp = reinterpret_cast<__nv_bfloat162*>(&ph[3]);
                pl[3] = packbf(p12 - __bfloat162float(hp->x), p13 - __bfloat162float(hp->y));
            }
#pragma unroll
            for (int nf2 = 0; nf2 < 4; nf2++) {
                uint32_t voff = (uint32_t)((t * 16 + (lane & 15)) * AT_STRIDE
                                           + nf2 * 16 + (lane >> 4) * 8) * 2;
                uint32_t vh4[4], vl4[4];
                ldm_x4_t(vh4, vbase + voff);
                ldm_x4_t(vl4, vbase + AT_TILE + voff);
                mma16816(o[2 * nf2],     ph, vh4[0], vh4[1]);
                mma16816(o[2 * nf2],     pl, vh4[0], vh4[1]);
                mma16816(o[2 * nf2],     ph, vl4[0], vl4[1]);
                mma16816(o[2 * nf2 + 1], ph, vh4[2], vh4[3]);
                mma16816(o[2 * nf2 + 1], pl, vh4[2], vh4[3]);
                mma16816(o[2 * nf2 + 1], ph, vl4[2], vl4[3]);
            }
        }
        sum0 += __shfl_xor_sync(0xffffffffu, sum0, 1);
        sum0 += __shfl_xor_sync(0xffffffffu, sum0, 2);
        sum1 += __shfl_xor_sync(0xffffffffu, sum1, 1);
        sum1 += __shfl_xor_sync(0xffffffffu, sum1, 2);
        l0 = l0 * a0 + sum0;
        l1 = l1 * a1 + sum1;
        __syncthreads();
    }

    // ---- epilogue: normalize, split to bf16 hi/lo, scatter to [B,N,D] ----
    float inv0 = 1.0f / l0, inv1 = 1.0f / l1;
    int q0 = blockIdx.x * 128 + wid * 16 + (lane >> 2);
    size_t row0 = (size_t)b * NSEQ + q0;
    size_t row1 = row0 + 8;
#pragma unroll
    for (int nf = 0; nf < 8; nf++) {
        int col = h * HD + nf * 8 + (lane & 3) * 2;
        float v0 = o[nf][0] * inv0, v1 = o[nf][1] * inv0;
        float v2 = o[nf][2] * inv1, v3 = o[nf][3] * inv1;
        __nv_bfloat16 h0 = __float2bfloat16(v0), h1 = __float2bfloat16(v1);
        __nv_bfloat16 h2 = __float2bfloat16(v2), h3 = __float2bfloat16(v3);
        *reinterpret_cast<__nv_bfloat162*>(&g_oh[row0 * DMODEL + col]) = __halves2bfloat162(h0, h1);
        *reinterpret_cast<__nv_bfloat162*>(&g_ol[row0 * DMODEL + col]) = __halves2bfloat162(
            __float2bfloat16(v0 - __bfloat162float(h0)),
            __float2bfloat16(v1 - __bfloat162float(h1)));
        *reinterpret_cast<__nv_bfloat162*>(&g_oh[row1 * DMODEL + col]) = __halves2bfloat162(h2, h3);
        *reinterpret_cast<__nv_bfloat162*>(&g_ol[row1 * DMODEL + col]) = __halves2bfloat162(
            __float2bfloat16(v2 - __bfloat162float(h2)),
            __float2bfloat16(v3 - __bfloat162float(h3)));
    }
}

// ---------------- launch ----------------
extern "C" void kernel_launch(void* const* d_in, const int* in_sizes, int n_in,
                              void* d_out, int out_size)
{
    const float* x       = (const float*)d_in[0];
    const float* cosT    = (const float*)d_in[1];
    const float* sinT    = (const float*)d_in[2];
    const float* Wqkv    = (const float*)d_in[3];
    const float* bqkv    = (const float*)d_in[4];
    const float* q_scale = (const float*)d_in[5];
    const float* k_scale = (const float*)d_in[6];
    const float* Wout    = (const float*)d_in[7];
    const float* bout    = (const float*)d_in[8];
    float* out = (float*)d_out;

    float* qkv_p;
    __nv_bfloat16 *xh_p, *xl_p, *oh_p, *ol_p, *wqh_p, *wql_p, *woh_p, *wol_p;
    cudaGetSymbolAddress((void**)&qkv_p, g_qkv);
    cudaGetSymbolAddress((void**)&xh_p, g_xh);
    cudaGetSymbolAddress((void**)&xl_p, g_xl);
    cudaGetSymbolAddress((void**)&oh_p, g_oh);
    cudaGetSymbolAddress((void**)&ol_p, g_ol);
    cudaGetSymbolAddress((void**)&wqh_p, g_wqh);
    cudaGetSymbolAddress((void**)&wql_p, g_wql);
    cudaGetSymbolAddress((void**)&woh_p, g_woh);
    cudaGetSymbolAddress((void**)&wol_p, g_wol);

    const int gemm_smem = 2 * STAGE_BYTES;                 // 81920
    cudaFuncSetAttribute(gemm_mma, cudaFuncAttributeMaxDynamicSharedMemorySize, gemm_smem);
    const int attn_smem = KV_BASE + 2 * KV_STAGE;          // 184320
    cudaFuncSetAttribute(attn_mma, cudaFuncAttributeMaxDynamicSharedMemorySize, attn_smem);

    // 0) splits
    split_kernel<<<(MROWS * DMODEL) / 1024, 256>>>(x, xh_p, xl_p, MROWS * DMODEL);
    trans_split_kernel<<<dim3(3 * DMODEL / 32, DMODEL / 32), 256>>>(
        Wqkv, wqh_p, wql_p, DMODEL, 3 * DMODEL);
    trans_split_kernel<<<dim3(DMODEL / 32, DMODEL / 32), 256>>>(
        Wout, woh_p, wol_p, DMODEL, DMODEL);

    // 1) QKV GEMM
    gemm_mma<<<dim3(3 * DMODEL / 128, MROWS / 128), 256, gemm_smem>>>(
        xh_p, xl_p, wqh_p, wql_p, bqkv, qkv_p, MROWS, 3 * DMODEL, DMODEL);

    // 2) RMSNorm + RoPE + split layout
    rms_rope_kernel<<<MROWS, 256>>>(cosT, sinT, q_scale, k_scale);

    // 3) Attention (mma.sync bf16x3, FFMA softmax)
    attn_mma<<<dim3(NSEQ / 128, NH, B_SZ), 256, attn_smem>>>();

    // 4) out-proj GEMM
    gemm_mma<<<dim3(DMODEL / 128, MROWS / 128), 256, gemm_smem>>>(
        oh_p, ol_p, woh_p, wol_p, bout, out, MROWS, DMODEL, DMODEL);
}

// round 6
// speedup vs baseline: 3.0343x; 1.1107x over previous
#include <cuda_runtime.h>
#include <cuda_bf16.h>
#include <cuda_fp16.h>
#include <cstdint>
#include <math.h>

#define B_SZ 2
#define NSEQ 2048
#define DMODEL 1024
#define NH 16
#define HD 64
#define MROWS (B_SZ * NSEQ)   // 4096

// ---------------- scratch (static device globals; no allocation) ----------------
__device__ float g_qkv[(size_t)MROWS * 3 * DMODEL];

// fp16 attention operands in [B,H,N,64]
__device__ __half g_q16h[(size_t)B_SZ * NH * NSEQ * HD];
__device__ __half g_q16l[(size_t)B_SZ * NH * NSEQ * HD];
__device__ __half g_k16[(size_t)B_SZ * NH * NSEQ * HD];
__device__ __half g_v16[(size_t)B_SZ * NH * NSEQ * HD];

// bf16 split GEMM operands
__device__ __nv_bfloat16 g_xh[(size_t)MROWS * DMODEL];
__device__ __nv_bfloat16 g_xl[(size_t)MROWS * DMODEL];
__device__ __nv_bfloat16 g_oh[(size_t)MROWS * DMODEL];
__device__ __nv_bfloat16 g_ol[(size_t)MROWS * DMODEL];
__device__ __nv_bfloat16 g_wqh[(size_t)3 * DMODEL * DMODEL];  // Wqkv^T
__device__ __nv_bfloat16 g_wql[(size_t)3 * DMODEL * DMODEL];
__device__ __nv_bfloat16 g_woh[(size_t)DMODEL * DMODEL];      // Wout^T
__device__ __nv_bfloat16 g_wol[(size_t)DMODEL * DMODEL];

// ---------------- helpers ----------------
__device__ __forceinline__ uint32_t smem_u32(const void* p) {
    uint32_t a;
    asm("{ .reg .u64 t; cvta.to.shared.u64 t, %1; cvt.u32.u64 %0, t; }"
        : "=r"(a) : "l"(p));
    return a;
}
__device__ __forceinline__ void cpa16(uint32_t s, const void* g) {
    asm volatile("cp.async.cg.shared.global [%0], [%1], 16;" :: "r"(s), "l"(g));
}
#define CP_COMMIT() asm volatile("cp.async.commit_group;" ::: "memory")
#define CP_WAIT(n)  asm volatile("cp.async.wait_group %0;" :: "n"(n) : "memory")

__device__ __forceinline__ void ldm_x4(uint32_t* r, uint32_t addr) {
    asm volatile("ldmatrix.sync.aligned.m8n8.x4.shared.b16 {%0,%1,%2,%3}, [%4];"
        : "=r"(r[0]), "=r"(r[1]), "=r"(r[2]), "=r"(r[3]) : "r"(addr));
}
__device__ __forceinline__ void ldm_x4_t(uint32_t* r, uint32_t addr) {
    asm volatile("ldmatrix.sync.aligned.m8n8.x4.trans.shared.b16 {%0,%1,%2,%3}, [%4];"
        : "=r"(r[0]), "=r"(r[1]), "=r"(r[2]), "=r"(r[3]) : "r"(addr));
}
__device__ __forceinline__ void mma_bf(float* d, const uint32_t* a,
                                       uint32_t b0, uint32_t b1) {
    asm volatile(
        "mma.sync.aligned.m16n8k16.row.col.f32.bf16.bf16.f32 "
        "{%0,%1,%2,%3}, {%4,%5,%6,%7}, {%8,%9}, {%0,%1,%2,%3};"
        : "+f"(d[0]), "+f"(d[1]), "+f"(d[2]), "+f"(d[3])
        : "r"(a[0]), "r"(a[1]), "r"(a[2]), "r"(a[3]), "r"(b0), "r"(b1));
}
__device__ __forceinline__ void mma_f16(float* d, const uint32_t* a,
                                        uint32_t b0, uint32_t b1) {
    asm volatile(
        "mma.sync.aligned.m16n8k16.row.col.f32.f16.f16.f32 "
        "{%0,%1,%2,%3}, {%4,%5,%6,%7}, {%8,%9}, {%0,%1,%2,%3};"
        : "+f"(d[0]), "+f"(d[1]), "+f"(d[2]), "+f"(d[3])
        : "r"(a[0]), "r"(a[1]), "r"(a[2]), "r"(a[3]), "r"(b0), "r"(b1));
}

// FFMA-only exp (MUFU rt=8 would bottleneck softmax)
__device__ __forceinline__ float fexp(float x) {
    x = fmaxf(x, -80.0f);
    float t = x * 1.4426950408889634f;
    float fm = t + 12582912.0f;
    int ii = __float_as_int(fm) << 23;
    float f = t - (fm - 12582912.0f);
    float p = 1.33335581e-3f;
    p = fmaf(p, f, 9.61812911e-3f);
    p = fmaf(p, f, 5.55041087e-2f);
    p = fmaf(p, f, 2.40226507e-1f);
    p = fmaf(p, f, 6.93147181e-1f);
    p = fmaf(p, f, 1.0f);
    return __int_as_float(__float_as_int(p) + ii);
}
__device__ __forceinline__ uint32_t packh(float a, float b) {
    __half2 t = __halves2half2(__float2half(a), __float2half(b));
    return *reinterpret_cast<uint32_t*>(&t);
}

// ---------------- split kernels ----------------
__global__ __launch_bounds__(256) void split_kernel(
    const float* __restrict__ s, __nv_bfloat16* __restrict__ h,
    __nv_bfloat16* __restrict__ l, int n)
{
    int i = (blockIdx.x * 256 + threadIdx.x) * 4;
    if (i >= n) return;
    float4 v = *reinterpret_cast<const float4*>(s + i);
    __nv_bfloat16 h0 = __float2bfloat16(v.x), h1 = __float2bfloat16(v.y);
    __nv_bfloat16 h2 = __float2bfloat16(v.z), h3 = __float2bfloat16(v.w);
    __nv_bfloat162* hp = reinterpret_cast<__nv_bfloat162*>(h + i);
    __nv_bfloat162* lp = reinterpret_cast<__nv_bfloat162*>(l + i);
    hp[0] = __halves2bfloat162(h0, h1);
    hp[1] = __halves2bfloat162(h2, h3);
    lp[0] = __halves2bfloat162(
        __float2bfloat16(v.x - __bfloat162float(h0)),
        __float2bfloat16(v.y - __bfloat162float(h1)));
    lp[1] = __halves2bfloat162(
        __float2bfloat16(v.z - __bfloat162float(h2)),
        __float2bfloat16(v.w - __bfloat162float(h3)));
}

__global__ __launch_bounds__(256) void trans_split_kernel(
    const float* __restrict__ W, __nv_bfloat16* __restrict__ Th,
    __nv_bfloat16* __restrict__ Tl, int K, int N)
{
    __shared__ float t[32][33];
    int n0 = blockIdx.x * 32, k0 = blockIdx.y * 32;
    int tx = threadIdx.x & 31, ty = threadIdx.x >> 5;
#pragma unroll
    for (int i = 0; i < 32; i += 8)
        t[ty + i][tx] = W[(size_t)(k0 + ty + i) * N + n0 + tx];
    __syncthreads();
#pragma unroll
    for (int i = 0; i < 32; i += 8) {
        float v = t[tx][ty + i];
        __nv_bfloat16 hh = __float2bfloat16(v);
        size_t o = (size_t)(n0 + ty + i) * K + k0 + tx;
        Th[o] = hh;
        Tl[o] = __float2bfloat16(v - __bfloat162float(hh));
    }
}

// ---------------- mma.sync bf16x3 GEMM (B frags via ldm_x4) ----------------
#define LDS_EL 40
#define OP_BYTES 10240
#define STAGE_BYTES (4 * OP_BYTES)

__global__ __launch_bounds__(256, 2) void gemm_mma(
    const __nv_bfloat16* __restrict__ Ah, const __nv_bfloat16* __restrict__ Al,
    const __nv_bfloat16* __restrict__ Bh, const __nv_bfloat16* __restrict__ Bl,
    const float* __restrict__ bias, float* __restrict__ C,
    int M, int N, int K)
{
    extern __shared__ char dsm[];
    const uint32_t sb = smem_u32(dsm);
    const int tid = threadIdx.x;
    const int lane = tid & 31;
    const int wid = tid >> 5;
    const int wm = wid & 3;
    const int wn = wid >> 2;
    const int rowBase = blockIdx.y * 128;
    const int colBase = blockIdx.x * 128;

    float acc[2][8][4];
#pragma unroll
    for (int i = 0; i < 2; i++)
#pragma unroll
        for (int j = 0; j < 8; j++)
#pragma unroll
            for (int c = 0; c < 4; c++) acc[i][j][c] = 0.0f;

    const int lr = tid >> 2;
    const int lc = tid & 3;

    auto load_stage = [&](int kc, int buf) {
        const int k0 = kc << 5;
        const uint32_t base = sb + (uint32_t)buf * STAGE_BYTES;
#pragma unroll
        for (int it = 0; it < 2; it++) {
            int row = it * 64 + lr;
            uint32_t so = (uint32_t)(row * LDS_EL + lc * 8) * 2;
            size_t ga = (size_t)(rowBase + row) * K + k0 + lc * 8;
            size_t gb = (size_t)(colBase + row) * K + k0 + lc * 8;
            cpa16(base + so,                Ah + ga);
            cpa16(base + OP_BYTES + so,     Al + ga);
            cpa16(base + 2 * OP_BYTES + so, Bh + gb);
            cpa16(base + 3 * OP_BYTES + so, Bl + gb);
        }
        CP_COMMIT();
    };

    auto compute_stage = [&](int buf) {
        const uint32_t base = sb + (uint32_t)buf * STAGE_BYTES;
#pragma unroll
        for (int ks = 0; ks < 2; ks++) {
            const int kcol = ks * 16;
            uint32_t ah[2][4], al[2][4];
#pragma unroll
            for (int mi = 0; mi < 2; mi++) {
                uint32_t off = (uint32_t)((wm * 32 + mi * 16 + (lane & 15)) * LDS_EL
                                          + kcol + (lane >> 4) * 8) * 2;
                ldm_x4(ah[mi], base + off);
                ldm_x4(al[mi], base + OP_BYTES + off);
            }
#pragma unroll
            for (int np = 0; np < 4; np++) {
                uint32_t boff = (uint32_t)((wn * 64 + np * 16 + (lane & 15)) * LDS_EL
                                           + kcol + (lane >> 4) * 8) * 2;
                uint32_t bh4[4], bl4[4];
                ldm_x4(bh4, base + 2 * OP_BYTES + boff);
                ldm_x4(bl4, base + 3 * OP_BYTES + boff);
#pragma unroll
                for (int mi = 0; mi < 2; mi++) {
                    mma_bf(acc[mi][2 * np],     ah[mi], bh4[0], bh4[2]);
                    mma_bf(acc[mi][2 * np],     al[mi], bh4[0], bh4[2]);
                    mma_bf(acc[mi][2 * np],     ah[mi], bl4[0], bl4[2]);
                    mma_bf(acc[mi][2 * np + 1], ah[mi], bh4[1], bh4[3]);
                    mma_bf(acc[mi][2 * np + 1], al[mi], bh4[1], bh4[3]);
                    mma_bf(acc[mi][2 * np + 1], ah[mi], bl4[1], bl4[3]);
                }
            }
        }
    };

    const int nK = K >> 5;
    load_stage(0, 0);
    for (int kc = 0; kc < nK; kc++) {
        const int buf = kc & 1;
        if (kc + 1 < nK) {
            load_stage(kc + 1, buf ^ 1);
            CP_WAIT(1);
        } else {
            CP_WAIT(0);
        }
        __syncthreads();
        compute_stage(buf);
        __syncthreads();
    }

#pragma unroll
    for (int mi = 0; mi < 2; mi++) {
        int row0 = rowBase + wm * 32 + mi * 16 + (lane >> 2);
#pragma unroll
        for (int ni = 0; ni < 8; ni++) {
            int col = colBase + wn * 64 + ni * 8 + (lane & 3) * 2;
            float2 bv = *reinterpret_cast<const float2*>(&bias[col]);
            float2 r0, r1;
            r0.x = acc[mi][ni][0] + bv.x;
            r0.y = acc[mi][ni][1] + bv.y;
            r1.x = acc[mi][ni][2] + bv.x;
            r1.y = acc[mi][ni][3] + bv.y;
            *reinterpret_cast<float2*>(&C[(size_t)row0 * N + col]) = r0;
            *reinterpret_cast<float2*>(&C[(size_t)(row0 + 8) * N + col]) = r1;
        }
    }
}

// ------------- fused RMSNorm + RoPE + fp16 head-layout scatter -------------
__global__ __launch_bounds__(256) void rms_rope_kernel(
    const float* __restrict__ cosT, const float* __restrict__ sinT,
    const float* __restrict__ q_scale, const float* __restrict__ k_scale)
{
    const int row = blockIdx.x;
    const int b = row / NSEQ;
    const int n = row % NSEQ;
    const float* qr = g_qkv + (size_t)row * 3 * DMODEL;
    const float* kr = qr + DMODEL;
    const float* vr = qr + 2 * DMODEL;

    float sq = 0.0f, sk = 0.0f;
    for (int i = threadIdx.x * 4; i < DMODEL; i += 256 * 4) {
        float4 q4 = *reinterpret_cast<const float4*>(&qr[i]);
        float4 k4 = *reinterpret_cast<const float4*>(&kr[i]);
        sq += q4.x * q4.x + q4.y * q4.y + q4.z * q4.z + q4.w * q4.w;
        sk += k4.x * k4.x + k4.y * k4.y + k4.z * k4.z + k4.w * k4.w;
    }
#pragma unroll
    for (int off = 16; off >= 1; off >>= 1) {
        sq += __shfl_xor_sync(0xffffffffu, sq, off);
        sk += __shfl_xor_sync(0xffffffffu, sk, off);
    }
    __shared__ float wq[8], wk[8];
    __shared__ float s_iq, s_ik;
    int wid = threadIdx.x >> 5, lid = threadIdx.x & 31;
    if (lid == 0) { wq[wid] = sq; wk[wid] = sk; }
    __syncthreads();
    if (threadIdx.x == 0) {
        float a = 0.0f, c = 0.0f;
#pragma unroll
        for (int w = 0; w < 8; w++) { a += wq[w]; c += wk[w]; }
        s_iq = rsqrtf(a / (float)DMODEL + 1e-6f);
        s_ik = rsqrtf(c / (float)DMODEL + 1e-6f);
    }
    __syncthreads();
    const float iq = s_iq, ik = s_ik;

    for (int p = threadIdx.x; p < DMODEL / 2; p += 256) {
        int h = p >> 5;
        int j = p & 31;
        int i0 = h * HD + 2 * j;
        float c = cosT[n * 32 + j];
        float s = sinT[n * 32 + j];
        float q0 = qr[i0]     * iq * q_scale[i0];
        float q1 = qr[i0 + 1] * iq * q_scale[i0 + 1];
        float k0 = kr[i0]     * ik * k_scale[i0];
        float k1 = kr[i0 + 1] * ik * k_scale[i0 + 1];
        float q0r = (q0 * c - q1 * s) * 0.125f;
        float q1r = (q0 * s + q1 * c) * 0.125f;
        float k0r = k0 * c - k1 * s;
        float k1r = k0 * s + k1 * c;
        size_t base = (((size_t)b * NH + h) * NSEQ + n) * HD + 2 * j;
        __half qh0 = __float2half(q0r), qh1 = __float2half(q1r);
        *reinterpret_cast<__half2*>(&g_q16h[base]) = __halves2half2(qh0, qh1);
        *reinterpret_cast<__half2*>(&g_q16l[base]) = __halves2half2(
            __float2half(q0r - __half2float(qh0)),
            __float2half(q1r - __half2float(qh1)));
        *reinterpret_cast<__half2*>(&g_k16[base]) =
            __halves2half2(__float2half(k0r), __float2half(k1r));
    }
    for (int i = threadIdx.x * 4; i < DMODEL; i += 1024) {
        float4 v4 = *reinterpret_cast<const float4*>(&vr[i]);
        int h = i >> 6;
        int c = i & 63;
        size_t base = (((size_t)b * NH + h) * NSEQ + n) * HD + c;
        *reinterpret_cast<__half2*>(&g_v16[base]) =
            __halves2half2(__float2half(v4.x), __float2half(v4.y));
        *reinterpret_cast<__half2*>(&g_v16[base + 2]) =
            __halves2half2(__float2half(v4.z), __float2half(v4.w));
    }
}

// ---------------- FA2 attention, fp16 2-pass mma.sync ----------------
// grid (32, NH, B), 128 threads = 4 warps, 64 q rows per CTA, 2 CTAs/SM.
// smem: Qh,Ql [64][72h]; 2 x {K [128][72h], V [128][72h]}.
#define AQ_STRIDE 72
#define AQ_TILE 9216           // 64*144
#define AKV_TILE 18432         // 128*144
#define AKV_BASE 18432         // after Qh,Ql
#define AKV_STAGE 36864        // K + V

__global__ __launch_bounds__(128, 2) void attn_f16()
{
    extern __shared__ char att_sm[];
    const uint32_t sb = smem_u32(att_sm);
    const int tid = threadIdx.x;
    const int lane = tid & 31;
    const int wid = tid >> 5;
    const int h = blockIdx.y, b = blockIdx.z;
    const size_t bh = ((size_t)b * NH + h) * (size_t)NSEQ * HD;
    const size_t q0g = bh + (size_t)blockIdx.x * 64 * HD;

    // Q tiles (hi, lo): 64 rows x 8 chunks x 2 tiles = 1024 loads / 128 thr
#pragma unroll
    for (int it = 0; it < 4; it++) {
        int id = it * 128 + tid;
        int r = id >> 3, ch = id & 7;
        uint32_t so = (uint32_t)(r * 144 + ch * 16);
        size_t g = q0g + (size_t)r * HD + ch * 8;
        cpa16(sb + so,           g_q16h + g);
        cpa16(sb + AQ_TILE + so, g_q16l + g);
    }
    CP_COMMIT();

    auto load_kv = [&](int kt, int buf) {
        const uint32_t base = sb + AKV_BASE + (uint32_t)buf * AKV_STAGE;
        size_t g0 = bh + (size_t)kt * 128 * HD;
#pragma unroll
        for (int it = 0; it < 8; it++) {
            int id = it * 128 + tid;
            int r = id >> 3, ch = id & 7;
            uint32_t so = (uint32_t)(r * 144 + ch * 16);
            size_t g = g0 + (size_t)r * HD + ch * 8;
            cpa16(base + so,            g_k16 + g);
            cpa16(base + AKV_TILE + so, g_v16 + g);
        }
        CP_COMMIT();
    };

    float m0 = -1e30f, m1 = -1e30f, l0 = 0.0f, l1 = 0.0f;
    float o[8][4];
#pragma unroll
    for (int i = 0; i < 8; i++)
#pragma unroll
        for (int c = 0; c < 4; c++) o[i][c] = 0.0f;

    load_kv(0, 0);

    for (int kt = 0; kt < NSEQ / 128; kt++) {
        const int buf = kt & 1;
        if (kt + 1 < NSEQ / 128) { load_kv(kt + 1, buf ^ 1); CP_WAIT(1); }
        else                     { CP_WAIT(0); }
        __syncthreads();

        const uint32_t kbase = sb + AKV_BASE + (uint32_t)buf * AKV_STAGE;
        const uint32_t vbase = kbase + AKV_TILE;

        // ---- S = (Q/8) K^T : 64x128 per CTA, 16x128 per warp, 2-pass ----
        float s[16][4];
#pragma unroll
        for (int i = 0; i < 16; i++)
#pragma unroll
            for (int c = 0; c < 4; c++) s[i][c] = 0.0f;

#pragma unroll
        for (int ks = 0; ks < 4; ks++) {
            uint32_t qoff = (uint32_t)((wid * 16 + (lane & 15)) * AQ_STRIDE
                                       + ks * 16 + (lane >> 4) * 8) * 2;
            uint32_t ah[4], al[4];
            ldm_x4(ah, sb + qoff);
            ldm_x4(al, sb + AQ_TILE + qoff);
#pragma unroll
            for (int nf2 = 0; nf2 < 8; nf2++) {
                uint32_t koff = (uint32_t)((nf2 * 16 + (lane & 15)) * AQ_STRIDE
                                           + ks * 16 + (lane >> 4) * 8) * 2;
                uint32_t kh4[4];
                ldm_x4(kh4, kbase + koff);
                mma_f16(s[2 * nf2],     ah, kh4[0], kh4[2]);
                mma_f16(s[2 * nf2],     al, kh4[0], kh4[2]);
                mma_f16(s[2 * nf2 + 1], ah, kh4[1], kh4[3]);
                mma_f16(s[2 * nf2 + 1], al, kh4[1], kh4[3]);
            }
        }

        // ---- online softmax ----
        float mx0 = -1e30f, mx1 = -1e30f;
#pragma unroll
        for (int nf = 0; nf < 16; nf++) {
            mx0 = fmaxf(mx0, fmaxf(s[nf][0], s[nf][1]));
            mx1 = fmaxf(mx1, fmaxf(s[nf][2], s[nf][3]));
        }
        mx0 = fmaxf(mx0, __shfl_xor_sync(0xffffffffu, mx0, 1));
        mx0 = fmaxf(mx0, __shfl_xor_sync(0xffffffffu, mx0, 2));
        mx1 = fmaxf(mx1, __shfl_xor_sync(0xffffffffu, mx1, 1));
        mx1 = fmaxf(mx1, __shfl_xor_sync(0xffffffffu, mx1, 2));
        float mn0 = fmaxf(m0, mx0), mn1 = fmaxf(m1, mx1);
        float a0 = fexp(m0 - mn0), a1 = fexp(m1 - mn1);
        m0 = mn0; m1 = mn1;
#pragma unroll
        for (int nf = 0; nf < 8; nf++) {
            o[nf][0] *= a0; o[nf][1] *= a0;
            o[nf][2] *= a1; o[nf][3] *= a1;
        }

        // ---- exp + pack (P hi/lo fp16) + PV 2-pass ----
        float sum0 = 0.0f, sum1 = 0.0f;
#pragma unroll
        for (int t = 0; t < 8; t++) {
            float p00 = fexp(s[2 * t][0] - mn0),     p01 = fexp(s[2 * t][1] - mn0);
            float p02 = fexp(s[2 * t][2] - mn1),     p03 = fexp(s[2 * t][3] - mn1);
            float p10 = fexp(s[2 * t + 1][0] - mn0), p11 = fexp(s[2 * t + 1][1] - mn0);
            float p12 = fexp(s[2 * t + 1][2] - mn1), p13 = fexp(s[2 * t + 1][3] - mn1);
            sum0 += (p00 + p01) + (p10 + p11);
            sum1 += (p02 + p03) + (p12 + p13);
            uint32_t ph[4], pl[4];
            ph[0] = packh(p00, p01); ph[1] = packh(p02, p03);
            ph[2] = packh(p10, p11); ph[3] = packh(p12, p13);
            {
                __half2* hp;
                hp = reinterpret_cast<__half2*>(&ph[0]);
                pl[0] = packh(p00 - __half2float(hp->x), p01 - __half2float(hp->y));
                hp = reinterpret_cast<__half2*>(&ph[1]);
                pl[1] = packh(p02 - __half2float(hp->x), p03 - __half2float(hp->y));
                hp = reinterpret_cast<__half2*>(&ph[2]);
                pl[2] = packh(p10 - __half2float(hp->x), p11 - __half2float(hp->y));
                hp = reinterpret_cast<__half2*>(&ph[3]);
                pl[3] = packh(p12 - __half2float(hp->x), p13 - __half2float(hp->y));
            }
#pragma unroll
            for (int nf2 = 0; nf2 < 4; nf2++) {
                uint32_t voff = (uint32_t)((t * 16 + (lane & 15)) * AQ_STRIDE
                                           + nf2 * 16 + (lane >> 4) * 8) * 2;
                uint32_t vh4[4];
                ldm_x4_t(vh4, vbase + voff);
                mma_f16(o[2 * nf2],     ph, vh4[0], vh4[1]);
                mma_f16(o[2 * nf2],     pl, vh4[0], vh4[1]);
                mma_f16(o[2 * nf2 + 1], ph, vh4[2], vh4[3]);
                mma_f16(o[2 * nf2 + 1], pl, vh4[2], vh4[3]);
            }
        }
        sum0 += __shfl_xor_sync(0xffffffffu, sum0, 1);
        sum0 += __shfl_xor_sync(0xffffffffu, sum0, 2);
        sum1 += __shfl_xor_sync(0xffffffffu, sum1, 1);
        sum1 += __shfl_xor_sync(0xffffffffu, sum1, 2);
        l0 = l0 * a0 + sum0;
        l1 = l1 * a1 + sum1;
        __syncthreads();
    }

    // ---- epilogue: normalize, split bf16 hi/lo for out-proj ----
    float inv0 = 1.0f / l0, inv1 = 1.0f / l1;
    int q0 = blockIdx.x * 64 + wid * 16 + (lane >> 2);
    size_t row0 = (size_t)b * NSEQ + q0;
    size_t row1 = row0 + 8;
#pragma unroll
    for (int nf = 0; nf < 8; nf++) {
        int col = h * HD + nf * 8 + (lane & 3) * 2;
        float v0 = o[nf][0] * inv0, v1 = o[nf][1] * inv0;
        float v2 = o[nf][2] * inv1, v3 = o[nf][3] * inv1;
        __nv_bfloat16 h0 = __float2bfloat16(v0), h1 = __float2bfloat16(v1);
        __nv_bfloat16 h2 = __float2bfloat16(v2), h3 = __float2bfloat16(v3);
        *reinterpret_cast<__nv_bfloat162*>(&g_oh[row0 * DMODEL + col]) = __halves2bfloat162(h0, h1);
        *reinterpret_cast<__nv_bfloat162*>(&g_ol[row0 * DMODEL + col]) = __halves2bfloat162(
            __float2bfloat16(v0 - __bfloat162float(h0)),
            __float2bfloat16(v1 - __bfloat162float(h1)));
        *reinterpret_cast<__nv_bfloat162*>(&g_oh[row1 * DMODEL + col]) = __halves2bfloat162(h2, h3);
        *reinterpret_cast<__nv_bfloat162*>(&g_ol[row1 * DMODEL + col]) = __halves2bfloat162(
            __float2bfloat16(v2 - __bfloat162float(h2)),
            __float2bfloat16(v3 - __bfloat162float(h3)));
    }
}

// ---------------- launch ----------------
extern "C" void kernel_launch(void* const* d_in, const int* in_sizes, int n_in,
                              void* d_out, int out_size)
{
    const float* x       = (const float*)d_in[0];
    const float* cosT    = (const float*)d_in[1];
    const float* sinT    = (const float*)d_in[2];
    const float* Wqkv    = (const float*)d_in[3];
    const float* bqkv    = (const float*)d_in[4];
    const float* q_scale = (const float*)d_in[5];
    const float* k_scale = (const float*)d_in[6];
    const float* Wout    = (const float*)d_in[7];
    const float* bout    = (const float*)d_in[8];
    float* out = (float*)d_out;

    float* qkv_p;
    __nv_bfloat16 *xh_p, *xl_p, *oh_p, *ol_p, *wqh_p, *wql_p, *woh_p, *wol_p;
    cudaGetSymbolAddress((void**)&qkv_p, g_qkv);
    cudaGetSymbolAddress((void**)&xh_p, g_xh);
    cudaGetSymbolAddress((void**)&xl_p, g_xl);
    cudaGetSymbolAddress((void**)&oh_p, g_oh);
    cudaGetSymbolAddress((void**)&ol_p, g_ol);
    cudaGetSymbolAddress((void**)&wqh_p, g_wqh);
    cudaGetSymbolAddress((void**)&wql_p, g_wql);
    cudaGetSymbolAddress((void**)&woh_p, g_woh);
    cudaGetSymbolAddress((void**)&wol_p, g_wol);

    const int gemm_smem = 2 * STAGE_BYTES;                 // 81920
    cudaFuncSetAttribute(gemm_mma, cudaFuncAttributeMaxDynamicSharedMemorySize, gemm_smem);
    const int attn_smem = AKV_BASE + 2 * AKV_STAGE;        // 92160
    cudaFuncSetAttribute(attn_f16, cudaFuncAttributeMaxDynamicSharedMemorySize, attn_smem);

    // 0) splits
    split_kernel<<<(MROWS * DMODEL) / 1024, 256>>>(x, xh_p, xl_p, MROWS * DMODEL);
    trans_split_kernel<<<dim3(3 * DMODEL / 32, DMODEL / 32), 256>>>(
        Wqkv, wqh_p, wql_p, DMODEL, 3 * DMODEL);
    trans_split_kernel<<<dim3(DMODEL / 32, DMODEL / 32), 256>>>(
        Wout, woh_p, wol_p, DMODEL, DMODEL);

    // 1) QKV GEMM (bf16x3)
    gemm_mma<<<dim3(3 * DMODEL / 128, MROWS / 128), 256, gemm_smem>>>(
        xh_p, xl_p, wqh_p, wql_p, bqkv, qkv_p, MROWS, 3 * DMODEL, DMODEL);

    // 2) RMSNorm + RoPE + fp16 layout
    rms_rope_kernel<<<MROWS, 256>>>(cosT, sinT, q_scale, k_scale);

    // 3) Attention (fp16 2-pass)
    attn_f16<<<dim3(NSEQ / 64, NH, B_SZ), 128, attn_smem>>>();

    // 4) out-proj GEMM (bf16x3)
    gemm_mma<<<dim3(DMODEL / 128, MROWS / 128), 256, gemm_smem>>>(
        oh_p, ol_p, woh_p, wol_p, bout, out, MROWS, DMODEL, DMODEL);
}

// round 7
// speedup vs baseline: 3.9683x; 1.3078x over previous
#include <cuda_runtime.h>
#include <cuda_bf16.h>
#include <cuda_fp16.h>
#include <cstdint>
#include <math.h>

#define B_SZ 2
#define NSEQ 2048
#define DMODEL 1024
#define NH 16
#define HD 64
#define MROWS (B_SZ * NSEQ)   // 4096

// ---------------- scratch (static device globals; no allocation) ----------------
__device__ float g_qkv[(size_t)MROWS * 3 * DMODEL];

// fp16 attention operands in [B,H,N,64]
__device__ __half g_q16h[(size_t)B_SZ * NH * NSEQ * HD];
__device__ __half g_q16l[(size_t)B_SZ * NH * NSEQ * HD];
__device__ __half g_k16[(size_t)B_SZ * NH * NSEQ * HD];
__device__ __half g_v16[(size_t)B_SZ * NH * NSEQ * HD];

// fp16 GEMM operands
__device__ __half g_xh[(size_t)MROWS * DMODEL];        // x hi
__device__ __half g_xl[(size_t)MROWS * DMODEL];        // x lo
__device__ __half g_oh[(size_t)MROWS * DMODEL];        // attn out hi
__device__ __half g_ol[(size_t)MROWS * DMODEL];        // attn out lo
__device__ __half g_wq16[(size_t)3 * DMODEL * DMODEL]; // Wqkv^T [3072][1024]
__device__ __half g_wo16[(size_t)DMODEL * DMODEL];     // Wout^T [1024][1024]

// ---------------- helpers ----------------
__device__ __forceinline__ uint32_t smem_u32(const void* p) {
    uint32_t a;
    asm("{ .reg .u64 t; cvta.to.shared.u64 t, %1; cvt.u32.u64 %0, t; }"
        : "=r"(a) : "l"(p));
    return a;
}
__device__ __forceinline__ void cpa16(uint32_t s, const void* g) {
    asm volatile("cp.async.cg.shared.global [%0], [%1], 16;" :: "r"(s), "l"(g));
}
#define CP_COMMIT() asm volatile("cp.async.commit_group;" ::: "memory")
#define CP_WAIT(n)  asm volatile("cp.async.wait_group %0;" :: "n"(n) : "memory")

__device__ __forceinline__ void ldm_x4(uint32_t* r, uint32_t addr) {
    asm volatile("ldmatrix.sync.aligned.m8n8.x4.shared.b16 {%0,%1,%2,%3}, [%4];"
        : "=r"(r[0]), "=r"(r[1]), "=r"(r[2]), "=r"(r[3]) : "r"(addr));
}
__device__ __forceinline__ void ldm_x4_t(uint32_t* r, uint32_t addr) {
    asm volatile("ldmatrix.sync.aligned.m8n8.x4.trans.shared.b16 {%0,%1,%2,%3}, [%4];"
        : "=r"(r[0]), "=r"(r[1]), "=r"(r[2]), "=r"(r[3]) : "r"(addr));
}
__device__ __forceinline__ void ldm_x2(uint32_t& r0, uint32_t& r1, uint32_t addr) {
    asm volatile("ldmatrix.sync.aligned.m8n8.x2.shared.b16 {%0,%1}, [%2];"
        : "=r"(r0), "=r"(r1) : "r"(addr));
}
__device__ __forceinline__ void mma_f16(float* d, const uint32_t* a,
                                        uint32_t b0, uint32_t b1) {
    asm volatile(
        "mma.sync.aligned.m16n8k16.row.col.f32.f16.f16.f32 "
        "{%0,%1,%2,%3}, {%4,%5,%6,%7}, {%8,%9}, {%0,%1,%2,%3};"
        : "+f"(d[0]), "+f"(d[1]), "+f"(d[2]), "+f"(d[3])
        : "r"(a[0]), "r"(a[1]), "r"(a[2]), "r"(a[3]), "r"(b0), "r"(b1));
}

// FFMA-only exp (MUFU rt=8 would bottleneck softmax)
__device__ __forceinline__ float fexp(float x) {
    x = fmaxf(x, -80.0f);
    float t = x * 1.4426950408889634f;
    float fm = t + 12582912.0f;
    int ii = __float_as_int(fm) << 23;
    float f = t - (fm - 12582912.0f);
    float p = 1.33335581e-3f;
    p = fmaf(p, f, 9.61812911e-3f);
    p = fmaf(p, f, 5.55041087e-2f);
    p = fmaf(p, f, 2.40226507e-1f);
    p = fmaf(p, f, 6.93147181e-1f);
    p = fmaf(p, f, 1.0f);
    return __int_as_float(__float_as_int(p) + ii);
}
__device__ __forceinline__ uint32_t packh(float a, float b) {
    __half2 t = __halves2half2(__float2half(a), __float2half(b));
    return *reinterpret_cast<uint32_t*>(&t);
}

// ---------------- operand prep kernels ----------------
// fp32 -> fp16 hi/lo split
__global__ __launch_bounds__(256) void split16_kernel(
    const float* __restrict__ s, __half* __restrict__ h,
    __half* __restrict__ l, int n)
{
    int i = (blockIdx.x * 256 + threadIdx.x) * 4;
    if (i >= n) return;
    float4 v = *reinterpret_cast<const float4*>(s + i);
    __half h0 = __float2half(v.x), h1 = __float2half(v.y);
    __half h2 = __float2half(v.z), h3 = __float2half(v.w);
    __half2* hp = reinterpret_cast<__half2*>(h + i);
    __half2* lp = reinterpret_cast<__half2*>(l + i);
    hp[0] = __halves2half2(h0, h1);
    hp[1] = __halves2half2(h2, h3);
    lp[0] = __halves2half2(__float2half(v.x - __half2float(h0)),
                           __float2half(v.y - __half2float(h1)));
    lp[1] = __halves2half2(__float2half(v.z - __half2float(h2)),
                           __float2half(v.w - __half2float(h3)));
}

// W[K][N] fp32 -> T [N][K] fp16 (transpose, single precision)
__global__ __launch_bounds__(256) void trans16_kernel(
    const float* __restrict__ W, __half* __restrict__ T, int K, int N)
{
    __shared__ float t[32][33];
    int n0 = blockIdx.x * 32, k0 = blockIdx.y * 32;
    int tx = threadIdx.x & 31, ty = threadIdx.x >> 5;
#pragma unroll
    for (int i = 0; i < 32; i += 8)
        t[ty + i][tx] = W[(size_t)(k0 + ty + i) * N + n0 + tx];
    __syncthreads();
#pragma unroll
    for (int i = 0; i < 32; i += 8)
        T[(size_t)(n0 + ty + i) * K + k0 + tx] = __float2half(t[tx][ty + i]);
}

// ---------------- mma.sync fp16 2-pass GEMM:  C = (Ah+Al) @ B^T + bias ----------------
// A: [M,K] fp16 hi/lo row-major. B: [N,K] fp16 row-major. C: [M,N] fp32.
// CTA 128x128, BK=32, 8 warps (4Mx2N), cp.async 2-stage. B frags via ldm_x2 (proven R4).
#define LDS_EL 40
#define OP_BYTES 10240            // 128 * 40 * 2
#define STAGE_BYTES (3 * OP_BYTES)

__global__ __launch_bounds__(256, 2) void gemm_mma(
    const __half* __restrict__ Ah, const __half* __restrict__ Al,
    const __half* __restrict__ B,
    const float* __restrict__ bias, float* __restrict__ C,
    int M, int N, int K)
{
    extern __shared__ char dsm[];
    const uint32_t sb = smem_u32(dsm);
    const int tid = threadIdx.x;
    const int lane = tid & 31;
    const int wid = tid >> 5;
    const int wm = wid & 3;
    const int wn = wid >> 2;
    const int rowBase = blockIdx.y * 128;
    const int colBase = blockIdx.x * 128;

    float acc[2][8][4];
#pragma unroll
    for (int i = 0; i < 2; i++)
#pragma unroll
        for (int j = 0; j < 8; j++)
#pragma unroll
            for (int c = 0; c < 4; c++) acc[i][j][c] = 0.0f;

    const int lr = tid >> 2;
    const int lc = tid & 3;

    auto load_stage = [&](int kc, int buf) {
        const int k0 = kc << 5;
        const uint32_t base = sb + (uint32_t)buf * STAGE_BYTES;
#pragma unroll
        for (int it = 0; it < 2; it++) {
            int row = it * 64 + lr;
            uint32_t so = (uint32_t)(row * LDS_EL + lc * 8) * 2;
            size_t ga = (size_t)(rowBase + row) * K + k0 + lc * 8;
            size_t gb = (size_t)(colBase + row) * K + k0 + lc * 8;
            cpa16(base + so,                Ah + ga);
            cpa16(base + OP_BYTES + so,     Al + ga);
            cpa16(base + 2 * OP_BYTES + so, B + gb);
        }
        CP_COMMIT();
    };

    auto compute_stage = [&](int buf) {
        const uint32_t base = sb + (uint32_t)buf * STAGE_BYTES;
#pragma unroll
        for (int ks = 0; ks < 2; ks++) {
            const int kcol = ks * 16;
            uint32_t ah[2][4], al[2][4];
#pragma unroll
            for (int mi = 0; mi < 2; mi++) {
                uint32_t off = (uint32_t)((wm * 32 + mi * 16 + (lane & 15)) * LDS_EL
                                          + kcol + (lane >> 4) * 8) * 2;
                ldm_x4(ah[mi], base + off);
                ldm_x4(al[mi], base + OP_BYTES + off);
            }
#pragma unroll
            for (int ni = 0; ni < 8; ni++) {
                uint32_t boff = (uint32_t)((wn * 64 + ni * 8 + (lane & 7)) * LDS_EL
                                           + kcol + ((lane >> 3) & 1) * 8) * 2;
                uint32_t b0, b1;
                ldm_x2(b0, b1, base + 2 * OP_BYTES + boff);
#pragma unroll
                for (int mi = 0; mi < 2; mi++) {
                    mma_f16(acc[mi][ni], ah[mi], b0, b1);
                    mma_f16(acc[mi][ni], al[mi], b0, b1);
                }
            }
        }
    };

    const int nK = K >> 5;
    load_stage(0, 0);
    for (int kc = 0; kc < nK; kc++) {
        const int buf = kc & 1;
        if (kc + 1 < nK) {
            load_stage(kc + 1, buf ^ 1);
            CP_WAIT(1);
        } else {
            CP_WAIT(0);
        }
        __syncthreads();
        compute_stage(buf);
        __syncthreads();
    }

#pragma unroll
    for (int mi = 0; mi < 2; mi++) {
        int row0 = rowBase + wm * 32 + mi * 16 + (lane >> 2);
#pragma unroll
        for (int ni = 0; ni < 8; ni++) {
            int col = colBase + wn * 64 + ni * 8 + (lane & 3) * 2;
            float2 bv = *reinterpret_cast<const float2*>(&bias[col]);
            float2 r0, r1;
            r0.x = acc[mi][ni][0] + bv.x;
            r0.y = acc[mi][ni][1] + bv.y;
            r1.x = acc[mi][ni][2] + bv.x;
            r1.y = acc[mi][ni][3] + bv.y;
            *reinterpret_cast<float2*>(&C[(size_t)row0 * N + col]) = r0;
            *reinterpret_cast<float2*>(&C[(size_t)(row0 + 8) * N + col]) = r1;
        }
    }
}

// ------------- fused RMSNorm + RoPE + fp16 head-layout scatter -------------
__global__ __launch_bounds__(256) void rms_rope_kernel(
    const float* __restrict__ cosT, const float* __restrict__ sinT,
    const float* __restrict__ q_scale, const float* __restrict__ k_scale)
{
    const int row = blockIdx.x;
    const int b = row / NSEQ;
    const int n = row % NSEQ;
    const float* qr = g_qkv + (size_t)row * 3 * DMODEL;
    const float* kr = qr + DMODEL;
    const float* vr = qr + 2 * DMODEL;

    float sq = 0.0f, sk = 0.0f;
    for (int i = threadIdx.x * 4; i < DMODEL; i += 256 * 4) {
        float4 q4 = *reinterpret_cast<const float4*>(&qr[i]);
        float4 k4 = *reinterpret_cast<const float4*>(&kr[i]);
        sq += q4.x * q4.x + q4.y * q4.y + q4.z * q4.z + q4.w * q4.w;
        sk += k4.x * k4.x + k4.y * k4.y + k4.z * k4.z + k4.w * k4.w;
    }
#pragma unroll
    for (int off = 16; off >= 1; off >>= 1) {
        sq += __shfl_xor_sync(0xffffffffu, sq, off);
        sk += __shfl_xor_sync(0xffffffffu, sk, off);
    }
    __shared__ float wq[8], wk[8];
    __shared__ float s_iq, s_ik;
    int wid = threadIdx.x >> 5, lid = threadIdx.x & 31;
    if (lid == 0) { wq[wid] = sq; wk[wid] = sk; }
    __syncthreads();
    if (threadIdx.x == 0) {
        float a = 0.0f, c = 0.0f;
#pragma unroll
        for (int w = 0; w < 8; w++) { a += wq[w]; c += wk[w]; }
        s_iq = rsqrtf(a / (float)DMODEL + 1e-6f);
        s_ik = rsqrtf(c / (float)DMODEL + 1e-6f);
    }
    __syncthreads();
    const float iq = s_iq, ik = s_ik;

    for (int p = threadIdx.x; p < DMODEL / 2; p += 256) {
        int h = p >> 5;
        int j = p & 31;
        int i0 = h * HD + 2 * j;
        float c = cosT[n * 32 + j];
        float s = sinT[n * 32 + j];
        float q0 = qr[i0]     * iq * q_scale[i0];
        float q1 = qr[i0 + 1] * iq * q_scale[i0 + 1];
        float k0 = kr[i0]     * ik * k_scale[i0];
        float k1 = kr[i0 + 1] * ik * k_scale[i0 + 1];
        float q0r = (q0 * c - q1 * s) * 0.125f;
        float q1r = (q0 * s + q1 * c) * 0.125f;
        float k0r = k0 * c - k1 * s;
        float k1r = k0 * s + k1 * c;
        size_t base = (((size_t)b * NH + h) * NSEQ + n) * HD + 2 * j;
        __half qh0 = __float2half(q0r), qh1 = __float2half(q1r);
        *reinterpret_cast<__half2*>(&g_q16h[base]) = __halves2half2(qh0, qh1);
        *reinterpret_cast<__half2*>(&g_q16l[base]) = __halves2half2(
            __float2half(q0r - __half2float(qh0)),
            __float2half(q1r - __half2float(qh1)));
        *reinterpret_cast<__half2*>(&g_k16[base]) =
            __halves2half2(__float2half(k0r), __float2half(k1r));
    }
    for (int i = threadIdx.x * 4; i < DMODEL; i += 1024) {
        float4 v4 = *reinterpret_cast<const float4*>(&vr[i]);
        int h = i >> 6;
        int c = i & 63;
        size_t base = (((size_t)b * NH + h) * NSEQ + n) * HD + c;
        *reinterpret_cast<__half2*>(&g_v16[base]) =
            __halves2half2(__float2half(v4.x), __float2half(v4.y));
        *reinterpret_cast<__half2*>(&g_v16[base + 2]) =
            __halves2half2(__float2half(v4.z), __float2half(v4.w));
    }
}

// ---------------- FA2 attention, fp16 2-pass mma.sync (R6, unchanged) ----------------
#define AQ_STRIDE 72
#define AQ_TILE 9216           // 64*144
#define AKV_TILE 18432         // 128*144
#define AKV_BASE 18432
#define AKV_STAGE 36864

__global__ __launch_bounds__(128, 2) void attn_f16()
{
    extern __shared__ char att_sm[];
    const uint32_t sb = smem_u32(att_sm);
    const int tid = threadIdx.x;
    const int lane = tid & 31;
    const int wid = tid >> 5;
    const int h = blockIdx.y, b = blockIdx.z;
    const size_t bh = ((size_t)b * NH + h) * (size_t)NSEQ * HD;
    const size_t q0g = bh + (size_t)blockIdx.x * 64 * HD;

#pragma unroll
    for (int it = 0; it < 4; it++) {
        int id = it * 128 + tid;
        int r = id >> 3, ch = id & 7;
        uint32_t so = (uint32_t)(r * 144 + ch * 16);
        size_t g = q0g + (size_t)r * HD + ch * 8;
        cpa16(sb + so,           g_q16h + g);
        cpa16(sb + AQ_TILE + so, g_q16l + g);
    }
    CP_COMMIT();

    auto load_kv = [&](int kt, int buf) {
        const uint32_t base = sb + AKV_BASE + (uint32_t)buf * AKV_STAGE;
        size_t g0 = bh + (size_t)kt * 128 * HD;
#pragma unroll
        for (int it = 0; it < 8; it++) {
            int id = it * 128 + tid;
            int r = id >> 3, ch = id & 7;
            uint32_t so = (uint32_t)(r * 144 + ch * 16);
            size_t g = g0 + (size_t)r * HD + ch * 8;
            cpa16(base + so,            g_k16 + g);
            cpa16(base + AKV_TILE + so, g_v16 + g);
        }
        CP_COMMIT();
    };

    float m0 = -1e30f, m1 = -1e30f, l0 = 0.0f, l1 = 0.0f;
    float o[8][4];
#pragma unroll
    for (int i = 0; i < 8; i++)
#pragma unroll
        for (int c = 0; c < 4; c++) o[i][c] = 0.0f;

    load_kv(0, 0);

    for (int kt = 0; kt < NSEQ / 128; kt++) {
        const int buf = kt & 1;
        if (kt + 1 < NSEQ / 128) { load_kv(kt + 1, buf ^ 1); CP_WAIT(1); }
        else                     { CP_WAIT(0); }
        __syncthreads();

        const uint32_t kbase = sb + AKV_BASE + (uint32_t)buf * AKV_STAGE;
        const uint32_t vbase = kbase + AKV_TILE;

        float s[16][4];
#pragma unroll
        for (int i = 0; i < 16; i++)
#pragma unroll
            for (int c = 0; c < 4; c++) s[i][c] = 0.0f;

#pragma unroll
        for (int ks = 0; ks < 4; ks++) {
            uint32_t qoff = (uint32_t)((wid * 16 + (lane & 15)) * AQ_STRIDE
                                       + ks * 16 + (lane >> 4) * 8) * 2;
            uint32_t ah[4], al[4];
            ldm_x4(ah, sb + qoff);
            ldm_x4(al, sb + AQ_TILE + qoff);
#pragma unroll
            for (int nf2 = 0; nf2 < 8; nf2++) {
                uint32_t koff = (uint32_t)((nf2 * 16 + (lane & 15)) * AQ_STRIDE
                                           + ks * 16 + (lane >> 4) * 8) * 2;
                uint32_t kh4[4];
                ldm_x4(kh4, kbase + koff);
                mma_f16(s[2 * nf2],     ah, kh4[0], kh4[2]);
                mma_f16(s[2 * nf2],     al, kh4[0], kh4[2]);
                mma_f16(s[2 * nf2 + 1], ah, kh4[1], kh4[3]);
                mma_f16(s[2 * nf2 + 1], al, kh4[1], kh4[3]);
            }
        }

        float mx0 = -1e30f, mx1 = -1e30f;
#pragma unroll
        for (int nf = 0; nf < 16; nf++) {
            mx0 = fmaxf(mx0, fmaxf(s[nf][0], s[nf][1]));
            mx1 = fmaxf(mx1, fmaxf(s[nf][2], s[nf][3]));
        }
        mx0 = fmaxf(mx0, __shfl_xor_sync(0xffffffffu, mx0, 1));
        mx0 = fmaxf(mx0, __shfl_xor_sync(0xffffffffu, mx0, 2));
        mx1 = fmaxf(mx1, __shfl_xor_sync(0xffffffffu, mx1, 1));
        mx1 = fmaxf(mx1, __shfl_xor_sync(0xffffffffu, mx1, 2));
        float mn0 = fmaxf(m0, mx0), mn1 = fmaxf(m1, mx1);
        float a0 = fexp(m0 - mn0), a1 = fexp(m1 - mn1);
        m0 = mn0; m1 = mn1;
#pragma unroll
        for (int nf = 0; nf < 8; nf++) {
            o[nf][0] *= a0; o[nf][1] *= a0;
            o[nf][2] *= a1; o[nf][3] *= a1;
        }

        float sum0 = 0.0f, sum1 = 0.0f;
#pragma unroll
        for (int t = 0; t < 8; t++) {
            float p00 = fexp(s[2 * t][0] - mn0),     p01 = fexp(s[2 * t][1] - mn0);
            float p02 = fexp(s[2 * t][2] - mn1),     p03 = fexp(s[2 * t][3] - mn1);
            float p10 = fexp(s[2 * t + 1][0] - mn0), p11 = fexp(s[2 * t + 1][1] - mn0);
            float p12 = fexp(s[2 * t + 1][2] - mn1), p13 = fexp(s[2 * t + 1][3] - mn1);
            sum0 += (p00 + p01) + (p10 + p11);
            sum1 += (p02 + p03) + (p12 + p13);
            uint32_t ph[4], pl[4];
            ph[0] = packh(p00, p01); ph[1] = packh(p02, p03);
            ph[2] = packh(p10, p11); ph[3] = packh(p12, p13);
            {
                __half2* hp;
                hp = reinterpret_cast<__half2*>(&ph[0]);
                pl[0] = packh(p00 - __half2float(hp->x), p01 - __half2float(hp->y));
                hp = reinterpret_cast<__half2*>(&ph[1]);
                pl[1] = packh(p02 - __half2float(hp->x), p03 - __half2float(hp->y));
                hp = reinterpret_cast<__half2*>(&ph[2]);
                pl[2] = packh(p10 - __half2float(hp->x), p11 - __half2float(hp->y));
                hp = reinterpret_cast<__half2*>(&ph[3]);
                pl[3] = packh(p12 - __half2float(hp->x), p13 - __half2float(hp->y));
            }
#pragma unroll
            for (int nf2 = 0; nf2 < 4; nf2++) {
                uint32_t voff = (uint32_t)((t * 16 + (lane & 15)) * AQ_STRIDE
                                           + nf2 * 16 + (lane >> 4) * 8) * 2;
                uint32_t vh4[4];
                ldm_x4_t(vh4, vbase + voff);
                mma_f16(o[2 * nf2],     ph, vh4[0], vh4[1]);
                mma_f16(o[2 * nf2],     pl, vh4[0], vh4[1]);
                mma_f16(o[2 * nf2 + 1], ph, vh4[2], vh4[3]);
                mma_f16(o[2 * nf2 + 1], pl, vh4[2], vh4[3]);
            }
        }
        sum0 += __shfl_xor_sync(0xffffffffu, sum0, 1);
        sum0 += __shfl_xor_sync(0xffffffffu, sum0, 2);
        sum1 += __shfl_xor_sync(0xffffffffu, sum1, 1);
        sum1 += __shfl_xor_sync(0xffffffffu, sum1, 2);
        l0 = l0 * a0 + sum0;
        l1 = l1 * a1 + sum1;
        __syncthreads();
    }

    // ---- epilogue: normalize, split fp16 hi/lo for out-proj ----
    float inv0 = 1.0f / l0, inv1 = 1.0f / l1;
    int q0 = blockIdx.x * 64 + wid * 16 + (lane >> 2);
    size_t row0 = (size_t)b * NSEQ + q0;
    size_t row1 = row0 + 8;
#pragma unroll
    for (int nf = 0; nf < 8; nf++) {
        int col = h * HD + nf * 8 + (lane & 3) * 2;
        float v0 = o[nf][0] * inv0, v1 = o[nf][1] * inv0;
        float v2 = o[nf][2] * inv1, v3 = o[nf][3] * inv1;
        __half h0 = __float2half(v0), h1 = __float2half(v1);
        __half h2 = __float2half(v2), h3 = __float2half(v3);
        *reinterpret_cast<__half2*>(&g_oh[row0 * DMODEL + col]) = __halves2half2(h0, h1);
        *reinterpret_cast<__half2*>(&g_ol[row0 * DMODEL + col]) = __halves2half2(
            __float2half(v0 - __half2float(h0)),
            __float2half(v1 - __half2float(h1)));
        *reinterpret_cast<__half2*>(&g_oh[row1 * DMODEL + col]) = __halves2half2(h2, h3);
        *reinterpret_cast<__half2*>(&g_ol[row1 * DMODEL + col]) = __halves2half2(
            __float2half(v2 - __half2float(h2)),
            __float2half(v3 - __half2float(h3)));
    }
}

// ---------------- launch ----------------
extern "C" void kernel_launch(void* const* d_in, const int* in_sizes, int n_in,
                              void* d_out, int out_size)
{
    const float* x       = (const float*)d_in[0];
    const float* cosT    = (const float*)d_in[1];
    const float* sinT    = (const float*)d_in[2];
    const float* Wqkv    = (const float*)d_in[3];
    const float* bqkv    = (const float*)d_in[4];
    const float* q_scale = (const float*)d_in[5];
    const float* k_scale = (const float*)d_in[6];
    const float* Wout    = (const float*)d_in[7];
    const float* bout    = (const float*)d_in[8];
    float* out = (float*)d_out;

    float* qkv_p;
    __half *xh_p, *xl_p, *oh_p, *ol_p, *wq_p, *wo_p;
    cudaGetSymbolAddress((void**)&qkv_p, g_qkv);
    cudaGetSymbolAddress((void**)&xh_p, g_xh);
    cudaGetSymbolAddress((void**)&xl_p, g_xl);
    cudaGetSymbolAddress((void**)&oh_p, g_oh);
    cudaGetSymbolAddress((void**)&ol_p, g_ol);
    cudaGetSymbolAddress((void**)&wq_p, g_wq16);
    cudaGetSymbolAddress((void**)&wo_p, g_wo16);

    const int gemm_smem = 2 * STAGE_BYTES;                 // 61440
    cudaFuncSetAttribute(gemm_mma, cudaFuncAttributeMaxDynamicSharedMemorySize, gemm_smem);
    const int attn_smem = AKV_BASE + 2 * AKV_STAGE;        // 92160
    cudaFuncSetAttribute(attn_f16, cudaFuncAttributeMaxDynamicSharedMemorySize, attn_smem);

    // 0) operand prep
    split16_kernel<<<(MROWS * DMODEL) / 1024, 256>>>(x, xh_p, xl_p, MROWS * DMODEL);
    trans16_kernel<<<dim3(3 * DMODEL / 32, DMODEL / 32), 256>>>(Wqkv, wq_p, DMODEL, 3 * DMODEL);
    trans16_kernel<<<dim3(DMODEL / 32, DMODEL / 32), 256>>>(Wout, wo_p, DMODEL, DMODEL);

    // 1) QKV GEMM (fp16 2-pass)
    gemm_mma<<<dim3(3 * DMODEL / 128, MROWS / 128), 256, gemm_smem>>>(
        xh_p, xl_p, wq_p, bqkv, qkv_p, MROWS, 3 * DMODEL, DMODEL);

    // 2) RMSNorm + RoPE + fp16 layout
    rms_rope_kernel<<<MROWS, 256>>>(cosT, sinT, q_scale, k_scale);

    // 3) Attention (fp16 2-pass)
    attn_f16<<<dim3(NSEQ / 64, NH, B_SZ), 128, attn_smem>>>();

    // 4) out-proj GEMM (fp16 2-pass)
    gemm_mma<<<dim3(DMODEL / 128, MROWS / 128), 256, gemm_smem>>>(
        oh_p, ol_p, wo_p, bout, out, MROWS, DMODEL, DMODEL);
}